// round 10
// baseline (speedup 1.0000x reference)
#include <cuda_runtime.h>
#include <cstdint>

#define NNODES 50000
#define EEDGES 1600000
#define DHID 128
#define DNF 128
#define DNG 64
#define LN2 0.69314718055994530942f
#define FPI 3.14159265358979323846f

typedef unsigned long long ull;

// Scratch (static device arrays: allocation-free per harness rules)
__device__ float g_h[(size_t)NNODES * DNF];    // x @ lin1_w
__device__ float g_agg[(size_t)NNODES * DNF];  // segment_sum accumulator
__device__ int   g_cnt;                        // compacted edge count
__device__ int   g_eid[EEDGES + 128];          // compacted: original edge id (padded)
__device__ int   g_src[EEDGES + 128];
__device__ int   g_dst[EEDGES + 128];
__device__ float g_C[EEDGES + 128];            // cutoff envelope

// ---------------- helpers ----------------
__device__ __forceinline__ float ssp_f(float v) {
    return fmaxf(v, 0.0f) + __logf(1.0f + __expf(-fabsf(v))) - LN2;
}
__device__ __forceinline__ void red_add_v4(float* p, float a, float b, float c, float d) {
    asm volatile("red.global.add.v4.f32 [%0], {%1, %2, %3, %4};"
                 :: "l"(p), "f"(a), "f"(b), "f"(c), "f"(d) : "memory");
}
__device__ __forceinline__ ull pack2(float a) {
    ull r;
    asm("mov.b64 %0, {%1, %1};" : "=l"(r) : "f"(a));
    return r;
}
__device__ __forceinline__ float2 unpack2(ull v) {
    float2 f;
    asm("mov.b64 {%0, %1}, %2;" : "=f"(f.x), "=f"(f.y) : "l"(v));
    return f;
}
__device__ __forceinline__ void fma2(ull& d, ull a, ull b) {
    asm("fma.rn.f32x2 %0, %1, %2, %0;" : "+l"(d) : "l"(a), "l"(b));
}
__device__ __forceinline__ float4 ldcs4(const float* p) {
    float4 v;
    asm volatile("ld.global.cs.v4.f32 {%0,%1,%2,%3}, [%4];"
                 : "=f"(v.x), "=f"(v.y), "=f"(v.z), "=f"(v.w) : "l"(p));
    return v;
}
__device__ __forceinline__ float4 ldcg4(const float* p) {
    float4 v;
    asm volatile("ld.global.cg.v4.f32 {%0,%1,%2,%3}, [%4];"
                 : "=f"(v.x), "=f"(v.y), "=f"(v.z), "=f"(v.w) : "l"(p));
    return v;
}

// ---- 2x8 microkernel, 512 threads / 128x128 tile, A and B both in smem ----
// rg = tid&31 (row pairs 2rg and 2rg+64), cg = tid>>5 in 0..15 (c0 = 8cg, uniform per warp).
// acc[j][c] = f32x2 row pair. As: [k][row] stride 130. Bs: [k][col] stride 128.
// Per warp-k: 2x LDS.64 (A) + 2x LDS.128 (B, full-warp broadcast) + 16 FFMA2 = 20 issues.
template <int K>
__device__ __forceinline__ void mm2x8(const float* __restrict__ As,
                                      const float* __restrict__ Bs,
                                      int rg2, int c0, ull acc[2][8]) {
#pragma unroll 4
    for (int k = 0; k < K; ++k) {
        const float* ar = As + k * 130 + rg2;
        ull a0 = *(const ull*)(ar);
        ull a1 = *(const ull*)(ar + 64);
        const float* br = Bs + k * 128 + c0;
        float4 b0 = *(const float4*)br;
        float4 b1 = *(const float4*)(br + 4);
        ull bb[8] = {pack2(b0.x), pack2(b0.y), pack2(b0.z), pack2(b0.w),
                     pack2(b1.x), pack2(b1.y), pack2(b1.z), pack2(b1.w)};
#pragma unroll
        for (int c = 0; c < 8; ++c) {
            fma2(acc[0][c], a0, bb[c]);
            fma2(acc[1][c], a1, bb[c]);
        }
    }
}

// ---- 8x8 microkernel, 256 threads, B from global/L1 (k_proj) ----
template <int K>
__device__ __forceinline__ void mm8x8g(const float* __restrict__ As,
                                       const float* __restrict__ Bg,
                                       int rg2, int c0, ull acc[4][8]) {
#pragma unroll 4
    for (int k = 0; k < K; ++k) {
        const float* ar = As + k * 130 + rg2;
        ull a0 = *(const ull*)(ar);
        ull a1 = *(const ull*)(ar + 32);
        ull a2 = *(const ull*)(ar + 64);
        ull a3 = *(const ull*)(ar + 96);
        const float4* bp = (const float4*)(Bg + k * 128 + c0);
        float4 b0 = __ldg(bp);
        float4 b1 = __ldg(bp + 1);
        ull bb[8] = {pack2(b0.x), pack2(b0.y), pack2(b0.z), pack2(b0.w),
                     pack2(b1.x), pack2(b1.y), pack2(b1.z), pack2(b1.w)};
#pragma unroll
        for (int c = 0; c < 8; ++c) {
            fma2(acc[0][c], a0, bb[c]);
            fma2(acc[1][c], a1, bb[c]);
            fma2(acc[2][c], a2, bb[c]);
            fma2(acc[3][c], a3, bb[c]);
        }
    }
}

// ---- 4x8 microkernel for k_out (512 threads, weights in smem) ----
template <int K>
__device__ __forceinline__ void mm4x8(const float* __restrict__ As,
                                      const float* __restrict__ Bs,
                                      int rg, int c0, ull acc[4][4]) {
#pragma unroll 4
    for (int k = 0; k < K; ++k) {
        const float* ar = As + k * 130 + rg;
        ull a0 = pack2(ar[0]);
        ull a1 = pack2(ar[32]);
        ull a2 = pack2(ar[64]);
        ull a3 = pack2(ar[96]);
        const float* br = Bs + k * 128 + c0;
        ulonglong2 b01 = *(const ulonglong2*)br;
        ulonglong2 b23 = *(const ulonglong2*)(br + 4);
        ull bb[4] = {b01.x, b01.y, b23.x, b23.y};
#pragma unroll
        for (int p = 0; p < 4; ++p) {
            fma2(acc[0][p], a0, bb[p]);
            fma2(acc[1][p], a1, bb[p]);
            fma2(acc[2][p], a2, bb[p]);
            fma2(acc[3][p], a3, bb[p]);
        }
    }
}

// ---------------- Kernel 0: compact edges with C != 0 ----------------
extern "C" __global__ void __launch_bounds__(256)
k_compact(const int* __restrict__ ei, const float* __restrict__ elen) {
    const int stride = gridDim.x * blockDim.x;
    const int i0 = blockIdx.x * blockDim.x + threadIdx.x;
    const int lane = threadIdx.x & 31;
    const int nit = (EEDGES + stride - 1) / stride;
    for (int it = 0; it < nit; ++it) {
        int i = i0 + it * stride;
        bool in = i < EEDGES;
        float L = in ? elen[i] : -1.0f;
        bool valid = in && (L <= 10.0f) && (L >= 0.0f);
        unsigned mask = __ballot_sync(0xffffffffu, valid);
        if (mask) {
            int leader = __ffs(mask) - 1;
            int base = 0;
            if (lane == leader) base = atomicAdd(&g_cnt, __popc(mask));
            base = __shfl_sync(0xffffffffu, base, leader);
            if (valid) {
                int pos = base + __popc(mask & ((1u << lane) - 1u));
                g_eid[pos] = i;
                g_src[pos] = ei[i];
                g_dst[pos] = ei[EEDGES + i];
                g_C[pos] = 0.5f * (__cosf(L * (FPI / 10.0f)) + 1.0f);
            }
        }
    }
}

// ---------------- Kernel 1: h = x @ lin1_w, zero g_agg + g_cnt ----------------
extern "C" __global__ void __launch_bounds__(256, 2)
k_proj_zero(const float* __restrict__ x, const float* __restrict__ w1) {
    extern __shared__ float sm[];
    float* sX = sm;                 // 128*130 transposed tile
    const int tid = threadIdx.x;
    const int cg = tid >> 4, rg = tid & 15;
    const int c0 = cg * 8, rg2 = rg * 2;

    if (blockIdx.x == 0 && tid == 0) g_cnt = 0;

    const int ntiles = (NNODES + 127) / 128;
    for (int tile = blockIdx.x; tile < ntiles; tile += gridDim.x) {
        const int r0 = tile * 128;
        __syncthreads();
        {
            int e = tid >> 1, k0 = (tid & 1) << 6;
            int r = r0 + e;
            if (r < NNODES) {
                const float* src = x + (size_t)r * DHID + k0;
#pragma unroll
                for (int i = 0; i < 16; ++i) {
                    float4 v = ldcs4(src + 4 * i);
                    int k = k0 + 4 * i;
                    sX[(k + 0) * 130 + e] = v.x;
                    sX[(k + 1) * 130 + e] = v.y;
                    sX[(k + 2) * 130 + e] = v.z;
                    sX[(k + 3) * 130 + e] = v.w;
                }
            }
        }
        __syncthreads();
        ull acc[4][8];
#pragma unroll
        for (int j = 0; j < 4; ++j)
#pragma unroll
            for (int c = 0; c < 8; ++c) acc[j][c] = 0ull;
        mm8x8g<DHID>(sX, w1, rg2, c0, acc);
#pragma unroll
        for (int j = 0; j < 4; ++j) {
            int r = r0 + rg2 + 32 * j;
            float2 v0 = unpack2(acc[j][0]), v1 = unpack2(acc[j][1]);
            float2 v2 = unpack2(acc[j][2]), v3 = unpack2(acc[j][3]);
            float2 v4 = unpack2(acc[j][4]), v5 = unpack2(acc[j][5]);
            float2 v6 = unpack2(acc[j][6]), v7 = unpack2(acc[j][7]);
            if (r < NNODES) {
                *(float4*)(g_h + (size_t)r * DNF + c0) = make_float4(v0.x, v1.x, v2.x, v3.x);
                *(float4*)(g_h + (size_t)r * DNF + c0 + 4) = make_float4(v4.x, v5.x, v6.x, v7.x);
                *(float4*)(g_agg + (size_t)r * DNF + c0) = make_float4(0.f, 0.f, 0.f, 0.f);
                *(float4*)(g_agg + (size_t)r * DNF + c0 + 4) = make_float4(0.f, 0.f, 0.f, 0.f);
            }
            if (r + 1 < NNODES) {
                *(float4*)(g_h + (size_t)(r + 1) * DNF + c0) = make_float4(v0.y, v1.y, v2.y, v3.y);
                *(float4*)(g_h + (size_t)(r + 1) * DNF + c0 + 4) = make_float4(v4.y, v5.y, v6.y, v7.y);
                *(float4*)(g_agg + (size_t)(r + 1) * DNF + c0) = make_float4(0.f, 0.f, 0.f, 0.f);
                *(float4*)(g_agg + (size_t)(r + 1) * DNF + c0 + 4) = make_float4(0.f, 0.f, 0.f, 0.f);
            }
        }
    }
}

// ---------------- Kernel 2: pipelined all-smem edge MLP + gather/scatter ----------------
// 512 threads, 1 CTA/SM. Weights + both tiles resident in smem (~195KB).
// Pipeline: GEMM1 | bar | LDG-pf | ssp->sT | bar | GEMM2 | STS-pf->sA | epilogue | bar
extern "C" __global__ void __launch_bounds__(512, 1)
k_edge(const float* __restrict__ edge_attr,
       const float* __restrict__ w1, const float* __restrict__ b1,
       const float* __restrict__ w2, const float* __restrict__ b2) {
    extern __shared__ float sm[];
    float* sW1 = sm;                  // 64*128  = 8192 f
    float* sW2 = sW1 + DNG * DNF;     // 128*128 = 16384 f
    float* sA  = sW2 + DNF * DNF;     // 64*130  = 8320 f
    float* sT  = sA + DNG * 130;      // 128*130 = 16640 f
    float* sB1 = sT + DNF * 130;      // 128
    float* sB2 = sB1 + 128;           // 128

    const int tid = threadIdx.x;
    const int rg = tid & 31, cg = tid >> 5;
    const int c0 = cg * 8, rg2 = rg * 2;
    const int e = tid >> 2, g0 = (tid & 3) << 4;   // A-load mapping

    // prologue: weights + biases
    for (int i = tid; i < DNG * DNF / 4; i += 512)
        ((float4*)sW1)[i] = ((const float4*)w1)[i];
    for (int i = tid; i < DNF * DNF / 4; i += 512)
        ((float4*)sW2)[i] = ((const float4*)w2)[i];
    if (tid < DNF) { sB1[tid] = b1[tid]; sB2[tid] = b2[tid]; }

    const int cnt = g_cnt;
    const int ntiles = (cnt + 127) >> 7;
    const int stride = gridDim.x;

    // prologue: first tile into sA
    int tile = blockIdx.x;
    if (tile < ntiles) {
        int gi = (tile << 7) + e;
        int eid = (gi < cnt) ? g_eid[gi] : 0;
        const float* src = edge_attr + (size_t)eid * DNG + g0;
#pragma unroll
        for (int i = 0; i < 4; ++i) {
            float4 v = ldcs4(src + 4 * i);
            int g = g0 + 4 * i;
            sA[(g + 0) * 130 + e] = v.x;
            sA[(g + 1) * 130 + e] = v.y;
            sA[(g + 2) * 130 + e] = v.z;
            sA[(g + 3) * 130 + e] = v.w;
        }
    }
    __syncthreads();

    for (; tile < ntiles; tile += stride) {
        const int eg0 = tile << 7;

        ull acc[2][8];
#pragma unroll
        for (int j = 0; j < 2; ++j)
#pragma unroll
            for (int c = 0; c < 8; ++c) acc[j][c] = 0ull;
        mm2x8<DNG>(sA, sW1, rg2, c0, acc);      // T = A @ W1
        __syncthreads();                         // sA reads done

        // --- issue next tile's LDGs (latency hidden behind ssp + GEMM2) ---
        const int nt = tile + stride;
        const bool have = nt < ntiles;           // CTA-uniform
        float4 pf[4];
        if (have) {
            int gi = (nt << 7) + e;
            int eid = (gi < cnt) ? g_eid[gi] : 0;
            const float* src = edge_attr + (size_t)eid * DNG + g0;
#pragma unroll
            for (int i = 0; i < 4; ++i) pf[i] = ldcs4(src + 4 * i);
        }

        // --- ssp(T + b1) -> sT transposed ---
#pragma unroll
        for (int c = 0; c < 8; ++c) {
            float bv = sB1[c0 + c];
            float2 v0 = unpack2(acc[0][c]);
            float2 v1 = unpack2(acc[1][c]);
            float* tp = sT + (c0 + c) * 130;
            *(float2*)(tp + rg2) = make_float2(ssp_f(v0.x + bv), ssp_f(v0.y + bv));
            *(float2*)(tp + rg2 + 64) = make_float2(ssp_f(v1.x + bv), ssp_f(v1.y + bv));
        }
        __syncthreads();                         // sT ready

#pragma unroll
        for (int j = 0; j < 2; ++j)
#pragma unroll
            for (int c = 0; c < 8; ++c) acc[j][c] = 0ull;
        mm2x8<DNF>(sT, sW2, rg2, c0, acc);      // Wmat = ssp(T) @ W2

        // --- store prefetched tile into sA (safe: GEMM1 reads ended at bar1) ---
        if (have) {
#pragma unroll
            for (int i = 0; i < 4; ++i) {
                int g = g0 + 4 * i;
                sA[(g + 0) * 130 + e] = pf[i].x;
                sA[(g + 1) * 130 + e] = pf[i].y;
                sA[(g + 2) * 130 + e] = pf[i].z;
                sA[(g + 3) * 130 + e] = pf[i].w;
            }
        }

        // --- epilogue: msg = (Wmat + b2)*C*h[src]; scatter-add to agg[dst] ---
        {
            float4 bA = *(const float4*)(sB2 + c0);
            float4 bB = *(const float4*)(sB2 + c0 + 4);
#pragma unroll
            for (int j = 0; j < 2; ++j) {
                int el = rg2 + 64 * j;
                int gi = eg0 + el;
                float2 cv = __ldg((const float2*)(g_C + gi));
                int2 srcp = __ldg((const int2*)(g_src + gi));
                int2 dstp = __ldg((const int2*)(g_dst + gi));
                float2 v0 = unpack2(acc[j][0]), v1 = unpack2(acc[j][1]);
                float2 v2 = unpack2(acc[j][2]), v3 = unpack2(acc[j][3]);
                float2 v4 = unpack2(acc[j][4]), v5 = unpack2(acc[j][5]);
                float2 v6 = unpack2(acc[j][6]), v7 = unpack2(acc[j][7]);
                if (gi < cnt && cv.x != 0.0f) {
                    const float* hp = g_h + (size_t)srcp.x * DNF + c0;
                    float4 h0 = ldcg4(hp);
                    float4 h1 = ldcg4(hp + 4);
                    float* dp = g_agg + (size_t)dstp.x * DNF + c0;
                    red_add_v4(dp, (v0.x + bA.x) * cv.x * h0.x, (v1.x + bA.y) * cv.x * h0.y,
                                   (v2.x + bA.z) * cv.x * h0.z, (v3.x + bA.w) * cv.x * h0.w);
                    red_add_v4(dp + 4, (v4.x + bB.x) * cv.x * h1.x, (v5.x + bB.y) * cv.x * h1.y,
                                       (v6.x + bB.z) * cv.x * h1.z, (v7.x + bB.w) * cv.x * h1.w);
                }
                if (gi + 1 < cnt && cv.y != 0.0f) {
                    const float* hp = g_h + (size_t)srcp.y * DNF + c0;
                    float4 h0 = ldcg4(hp);
                    float4 h1 = ldcg4(hp + 4);
                    float* dp = g_agg + (size_t)dstp.y * DNF + c0;
                    red_add_v4(dp, (v0.y + bA.x) * cv.y * h0.x, (v1.y + bA.y) * cv.y * h0.y,
                                   (v2.y + bA.z) * cv.y * h0.z, (v3.y + bA.w) * cv.y * h0.w);
                    red_add_v4(dp + 4, (v4.y + bB.x) * cv.y * h1.x, (v5.y + bB.y) * cv.y * h1.y,
                                       (v6.y + bB.z) * cv.y * h1.z, (v7.y + bB.w) * cv.y * h1.w);
                }
            }
        }
        __syncthreads();   // sA (next tile) + sT reads complete
    }
}

// -------- Kernel 3: out = ssp(agg@lin2_w + lin2_b) @ lin_w + lin_b --------
extern "C" __global__ void __launch_bounds__(512, 1)
k_out(const float* __restrict__ w2, const float* __restrict__ b2,
      const float* __restrict__ w3, const float* __restrict__ b3,
      float* __restrict__ out) {
    extern __shared__ float sm[];
    float* sW2 = sm;                  // 128*128 (lin2_w)
    float* sW3 = sW2 + DNF * DHID;    // 128*128 (lin_w)
    float* sA  = sW3 + DHID * DHID;   // 128*130 (aliased A then T)
    float* sB2 = sA + DNF * 130;      // 128
    float* sB3 = sB2 + 128;           // 128

    const int tid = threadIdx.x;
    const int rg = tid & 31, cg = tid >> 5;
    const int c0 = cg * 8;

    for (int i = tid; i < DNF * DHID / 4; i += 512)
        ((float4*)sW2)[i] = ((const float4*)w2)[i];
    for (int i = tid; i < DHID * DHID / 4; i += 512)
        ((float4*)sW3)[i] = ((const float4*)w3)[i];
    if (tid < DHID) { sB2[tid] = b2[tid]; sB3[tid] = b3[tid]; }

    const int ntiles = (NNODES + 127) / 128;
    for (int tile = blockIdx.x; tile < ntiles; tile += gridDim.x) {
        const int r0 = tile * 128;
        __syncthreads();
        {
            int e = tid >> 2, k0 = (tid & 3) << 5;
            int r = r0 + e;
            const float* src = g_agg + (size_t)r * DNF + k0;
#pragma unroll
            for (int i = 0; i < 8; ++i) {
                float4 v = (r < NNODES) ? ldcs4(src + 4 * i) : make_float4(0.f, 0.f, 0.f, 0.f);
                int k = k0 + 4 * i;
                sA[(k + 0) * 130 + e] = v.x;
                sA[(k + 1) * 130 + e] = v.y;
                sA[(k + 2) * 130 + e] = v.z;
                sA[(k + 3) * 130 + e] = v.w;
            }
        }
        __syncthreads();

        ull acc[4][4];
#pragma unroll
        for (int j = 0; j < 4; ++j)
#pragma unroll
            for (int p = 0; p < 4; ++p) acc[j][p] = 0ull;
        mm4x8<DNF>(sA, sW2, rg, c0, acc);
        __syncthreads();

#pragma unroll
        for (int p = 0; p < 4; ++p) {
            float bx = sB2[c0 + 2 * p], by = sB2[c0 + 2 * p + 1];
#pragma unroll
            for (int j = 0; j < 4; ++j) {
                float2 v = unpack2(acc[j][p]);
                int row = rg + 32 * j;
                sA[(c0 + 2 * p) * 130 + row] = ssp_f(v.x + bx);
                sA[(c0 + 2 * p + 1) * 130 + row] = ssp_f(v.y + by);
            }
        }
        __syncthreads();

#pragma unroll
        for (int j = 0; j < 4; ++j)
#pragma unroll
            for (int p = 0; p < 4; ++p) acc[j][p] = 0ull;
        mm4x8<DHID>(sA, sW3, rg, c0, acc);

#pragma unroll
        for (int j = 0; j < 4; ++j) {
            int r = r0 + rg + 32 * j;
            if (r < NNODES) {
                float2 v0 = unpack2(acc[j][0]), v1 = unpack2(acc[j][1]);
                float2 v2 = unpack2(acc[j][2]), v3 = unpack2(acc[j][3]);
                *(float4*)(out + (size_t)r * DHID + c0) =
                    make_float4(v0.x + sB3[c0 + 0], v0.y + sB3[c0 + 1],
                                v1.x + sB3[c0 + 2], v1.y + sB3[c0 + 3]);
                *(float4*)(out + (size_t)r * DHID + c0 + 4) =
                    make_float4(v2.x + sB3[c0 + 4], v2.y + sB3[c0 + 5],
                                v3.x + sB3[c0 + 6], v3.y + sB3[c0 + 7]);
            }
        }
    }
}

extern "C" void kernel_launch(void* const* d_in, const int* in_sizes, int n_in,
                              void* d_out, int out_size) {
    const float* x      = (const float*)d_in[0];
    const int*   ei     = (const int*)d_in[1];
    const float* elen   = (const float*)d_in[2];
    const float* eattr  = (const float*)d_in[3];
    const float* lin1_w = (const float*)d_in[4];
    const float* nn_w1  = (const float*)d_in[5];
    const float* nn_b1  = (const float*)d_in[6];
    const float* nn_w2  = (const float*)d_in[7];
    const float* nn_b2  = (const float*)d_in[8];
    const float* lin2_w = (const float*)d_in[9];
    const float* lin2_b = (const float*)d_in[10];
    const float* lin_w  = (const float*)d_in[11];
    const float* lin_b  = (const float*)d_in[12];
    float* out = (float*)d_out;

    size_t sm1 = (size_t)(DHID * 130) * 4;                                      // 66560
    size_t sm2 = (size_t)(DNG * DNF + DNF * DNF + DNG * 130 + DNF * 130 + 256) * 4;  // ~199KB
    size_t sm3 = (size_t)(DNF * DHID + DHID * DHID + DNF * 130 + 2 * 128) * 4;

    cudaFuncSetAttribute(k_proj_zero, cudaFuncAttributeMaxDynamicSharedMemorySize, (int)sm1);
    cudaFuncSetAttribute(k_edge, cudaFuncAttributeMaxDynamicSharedMemorySize, (int)sm2);
    cudaFuncSetAttribute(k_out, cudaFuncAttributeMaxDynamicSharedMemorySize, (int)sm3);

    k_proj_zero<<<304, 256, sm1>>>(x, lin1_w);          // also zeroes g_cnt + g_agg
    k_compact<<<152, 256>>>(ei, elen);
    k_edge<<<152, 512, sm2>>>(eattr, nn_w1, nn_b1, nn_w2, nn_b2);
    k_out<<<152, 512, sm3>>>(lin2_w, lin2_b, lin_w, lin_b, out);
}

// round 11
// speedup vs baseline: 1.0083x; 1.0083x over previous
#include <cuda_runtime.h>
#include <cstdint>

#define NNODES 50000
#define EEDGES 1600000
#define DHID 128
#define DNF 128
#define DNG 64
#define LN2 0.69314718055994530942f
#define FPI 3.14159265358979323846f

typedef unsigned long long ull;

// Scratch (static device arrays: allocation-free per harness rules)
__device__ float g_h[(size_t)NNODES * DNF];    // x @ lin1_w
__device__ float g_agg[(size_t)NNODES * DNF];  // segment_sum accumulator
__device__ int   g_cnt;                        // compacted edge count
__device__ int   g_hist[NNODES];               // per-dst edge count
__device__ int   g_off[NNODES];                // exclusive prefix (mutated by scatter)
__device__ int   g_eid[EEDGES + 128];          // dst-sorted: original edge id (padded)
__device__ int   g_src[EEDGES + 128];
__device__ int   g_dst[EEDGES + 128];
__device__ float g_C[EEDGES + 128];            // cutoff envelope

// ---------------- helpers ----------------
__device__ __forceinline__ float ssp_f(float v) {
    return fmaxf(v, 0.0f) + __logf(1.0f + __expf(-fabsf(v))) - LN2;
}
__device__ __forceinline__ void red_add_v4(float* p, float a, float b, float c, float d) {
    asm volatile("red.global.add.v4.f32 [%0], {%1, %2, %3, %4};"
                 :: "l"(p), "f"(a), "f"(b), "f"(c), "f"(d) : "memory");
}
__device__ __forceinline__ ull pack2(float a) {
    ull r;
    asm("mov.b64 %0, {%1, %1};" : "=l"(r) : "f"(a));
    return r;
}
__device__ __forceinline__ float2 unpack2(ull v) {
    float2 f;
    asm("mov.b64 {%0, %1}, %2;" : "=f"(f.x), "=f"(f.y) : "l"(v));
    return f;
}
__device__ __forceinline__ void fma2(ull& d, ull a, ull b) {
    asm("fma.rn.f32x2 %0, %1, %2, %0;" : "+l"(d) : "l"(a), "l"(b));
}
__device__ __forceinline__ float4 ldcs4(const float* p) {
    float4 v;
    asm volatile("ld.global.cs.v4.f32 {%0,%1,%2,%3}, [%4];"
                 : "=f"(v.x), "=f"(v.y), "=f"(v.z), "=f"(v.w) : "l"(p));
    return v;
}
__device__ __forceinline__ float4 ldcg4(const float* p) {
    float4 v;
    asm volatile("ld.global.cg.v4.f32 {%0,%1,%2,%3}, [%4];"
                 : "=f"(v.x), "=f"(v.y), "=f"(v.z), "=f"(v.w) : "l"(p));
    return v;
}

// ---- 8x8 microkernel, 256 threads / 128x128 tile, B streamed from GLOBAL (L1-resident) ----
// cg = tid>>4 (c0=8cg), rg = tid&15 (row pairs rg2, +32, +64, +96).
// acc[j][c] = f32x2 row-pair. As: [k][row] stride 130. Bg: [k][col] stride 128.
template <int K>
__device__ __forceinline__ void mm8x8g(const float* __restrict__ As,
                                       const float* __restrict__ Bg,
                                       int rg2, int c0, ull acc[4][8]) {
#pragma unroll 4
    for (int k = 0; k < K; ++k) {
        const float* ar = As + k * 130 + rg2;
        ull a0 = *(const ull*)(ar);
        ull a1 = *(const ull*)(ar + 32);
        ull a2 = *(const ull*)(ar + 64);
        ull a3 = *(const ull*)(ar + 96);
        const float4* bp = (const float4*)(Bg + k * 128 + c0);
        float4 b0 = __ldg(bp);
        float4 b1 = __ldg(bp + 1);
        ull bb[8] = {pack2(b0.x), pack2(b0.y), pack2(b0.z), pack2(b0.w),
                     pack2(b1.x), pack2(b1.y), pack2(b1.z), pack2(b1.w)};
#pragma unroll
        for (int c = 0; c < 8; ++c) {
            fma2(acc[0][c], a0, bb[c]);
            fma2(acc[1][c], a1, bb[c]);
            fma2(acc[2][c], a2, bb[c]);
            fma2(acc[3][c], a3, bb[c]);
        }
    }
}

__device__ __forceinline__ void zero_acc8(ull acc[4][8]) {
#pragma unroll
    for (int j = 0; j < 4; ++j)
#pragma unroll
        for (int c = 0; c < 8; ++c) acc[j][c] = 0ull;
}

// ---- 4x8 microkernel for k_out (512 threads, weights in smem) ----
template <int K>
__device__ __forceinline__ void mm4x8(const float* __restrict__ As,
                                      const float* __restrict__ Bs,
                                      int rg, int c0, ull acc[4][4]) {
#pragma unroll 4
    for (int k = 0; k < K; ++k) {
        const float* ar = As + k * 130 + rg;
        ull a0 = pack2(ar[0]);
        ull a1 = pack2(ar[32]);
        ull a2 = pack2(ar[64]);
        ull a3 = pack2(ar[96]);
        const float* br = Bs + k * 128 + c0;
        ulonglong2 b01 = *(const ulonglong2*)br;
        ulonglong2 b23 = *(const ulonglong2*)(br + 4);
        ull bb[4] = {b01.x, b01.y, b23.x, b23.y};
#pragma unroll
        for (int p = 0; p < 4; ++p) {
            fma2(acc[0][p], a0, bb[p]);
            fma2(acc[1][p], a1, bb[p]);
            fma2(acc[2][p], a2, bb[p]);
            fma2(acc[3][p], a3, bb[p]);
        }
    }
}

// ---------------- Kernel S1: per-dst histogram of valid edges ----------------
extern "C" __global__ void __launch_bounds__(256)
k_count(const int* __restrict__ ei, const float* __restrict__ elen) {
    const int stride = gridDim.x * blockDim.x;
    for (int i = blockIdx.x * blockDim.x + threadIdx.x; i < EEDGES; i += stride) {
        float L = elen[i];
        if (L <= 10.0f && L >= 0.0f)
            atomicAdd(&g_hist[ei[EEDGES + i]], 1);
    }
}

// ---------------- Kernel S2: exclusive prefix sum over 50K bins (1 CTA) ----------------
extern "C" __global__ void __launch_bounds__(1024)
k_scan() {
    __shared__ int s[1024];
    const int tid = threadIdx.x;
    int running = 0;
    for (int base = 0; base < NNODES; base += 1024) {
        int idx = base + tid;
        int v = (idx < NNODES) ? g_hist[idx] : 0;
        s[tid] = v;
        __syncthreads();
#pragma unroll
        for (int off = 1; off < 1024; off <<= 1) {
            int t = (tid >= off) ? s[tid - off] : 0;
            __syncthreads();
            s[tid] += t;
            __syncthreads();
        }
        if (idx < NNODES) g_off[idx] = running + s[tid] - v;   // exclusive
        int tot = s[1023];
        __syncthreads();
        running += tot;
    }
    if (tid == 0) g_cnt = running;
}

// ---------------- Kernel S3: scatter edges to dst-sorted positions ----------------
extern "C" __global__ void __launch_bounds__(256)
k_scatter(const int* __restrict__ ei, const float* __restrict__ elen) {
    const int stride = gridDim.x * blockDim.x;
    for (int i = blockIdx.x * blockDim.x + threadIdx.x; i < EEDGES; i += stride) {
        float L = elen[i];
        if (L <= 10.0f && L >= 0.0f) {
            int d = ei[EEDGES + i];
            int pos = atomicAdd(&g_off[d], 1);
            g_eid[pos] = i;
            g_src[pos] = ei[i];
            g_dst[pos] = d;
            g_C[pos] = 0.5f * (__cosf(L * (FPI / 10.0f)) + 1.0f);
        }
    }
}

// ---------------- Kernel 1: h = x @ lin1_w, zero g_agg + g_hist ----------------
extern "C" __global__ void __launch_bounds__(256, 2)
k_proj_zero(const float* __restrict__ x, const float* __restrict__ w1) {
    extern __shared__ float sm[];
    float* sX = sm;                 // 128*130 transposed tile
    const int tid = threadIdx.x;
    const int cg = tid >> 4, rg = tid & 15;
    const int c0 = cg * 8, rg2 = rg * 2;

    const int ntiles = (NNODES + 127) / 128;
    for (int tile = blockIdx.x; tile < ntiles; tile += gridDim.x) {
        const int r0 = tile * 128;
        __syncthreads();
        {
            int e = tid >> 1, k0 = (tid & 1) << 6;
            int r = r0 + e;
            if (r < NNODES) {
                const float* src = x + (size_t)r * DHID + k0;
#pragma unroll
                for (int i = 0; i < 16; ++i) {
                    float4 v = ldcs4(src + 4 * i);
                    int k = k0 + 4 * i;
                    sX[(k + 0) * 130 + e] = v.x;
                    sX[(k + 1) * 130 + e] = v.y;
                    sX[(k + 2) * 130 + e] = v.z;
                    sX[(k + 3) * 130 + e] = v.w;
                }
            }
        }
        __syncthreads();
        ull acc[4][8];
        zero_acc8(acc);
        mm8x8g<DHID>(sX, w1, rg2, c0, acc);
#pragma unroll
        for (int j = 0; j < 4; ++j) {
            int r = r0 + rg2 + 32 * j;
            float2 v0 = unpack2(acc[j][0]), v1 = unpack2(acc[j][1]);
            float2 v2 = unpack2(acc[j][2]), v3 = unpack2(acc[j][3]);
            float2 v4 = unpack2(acc[j][4]), v5 = unpack2(acc[j][5]);
            float2 v6 = unpack2(acc[j][6]), v7 = unpack2(acc[j][7]);
            if (r < NNODES) {
                *(float4*)(g_h + (size_t)r * DNF + c0) = make_float4(v0.x, v1.x, v2.x, v3.x);
                *(float4*)(g_h + (size_t)r * DNF + c0 + 4) = make_float4(v4.x, v5.x, v6.x, v7.x);
                *(float4*)(g_agg + (size_t)r * DNF + c0) = make_float4(0.f, 0.f, 0.f, 0.f);
                *(float4*)(g_agg + (size_t)r * DNF + c0 + 4) = make_float4(0.f, 0.f, 0.f, 0.f);
                if (cg == 0) g_hist[r] = 0;
            }
            if (r + 1 < NNODES) {
                *(float4*)(g_h + (size_t)(r + 1) * DNF + c0) = make_float4(v0.y, v1.y, v2.y, v3.y);
                *(float4*)(g_h + (size_t)(r + 1) * DNF + c0 + 4) = make_float4(v4.y, v5.y, v6.y, v7.y);
                *(float4*)(g_agg + (size_t)(r + 1) * DNF + c0) = make_float4(0.f, 0.f, 0.f, 0.f);
                *(float4*)(g_agg + (size_t)(r + 1) * DNF + c0 + 4) = make_float4(0.f, 0.f, 0.f, 0.f);
                if (cg == 0) g_hist[r + 1] = 0;
            }
        }
    }
}

// ---------------- Kernel 2: edge MLP + gather/scatter over dst-sorted edges ----------------
// smem = ONLY the 128x130 tile union (66560 B) so 2 CTAs fit; weights stay L1-resident.
// Epilogue merges the RED pair when adjacent (sorted) edges share dst (~96% of pairs).
extern "C" __global__ void __launch_bounds__(256, 2)
k_edge(const float* __restrict__ edge_attr,
       const float* __restrict__ w1, const float* __restrict__ b1,
       const float* __restrict__ w2, const float* __restrict__ b2) {
    extern __shared__ float sm[];
    float* sTile = sm;     // union: sA (first 64 rows) / sT (128 rows), stride 130

    const int tid = threadIdx.x;
    const int cg = tid >> 4, rg = tid & 15;
    const int c0 = cg * 8, rg2 = rg * 2;

    const int cnt = g_cnt;
    const int ntiles = (cnt + 127) >> 7;
    for (int tile = blockIdx.x; tile < ntiles; tile += gridDim.x) {
        const int eg0 = tile << 7;
        __syncthreads();   // prev tile GEMM2 done with sT
        {
            int e = tid >> 1, g0 = (tid & 1) << 5;
            int gi = eg0 + e;
            int eid = (gi < cnt) ? g_eid[gi] : 0;
            const float* src = edge_attr + (size_t)eid * DNG + g0;
#pragma unroll
            for (int i = 0; i < 8; ++i) {
                float4 v = ldcs4(src + 4 * i);
                int g = g0 + 4 * i;
                sTile[(g + 0) * 130 + e] = v.x;
                sTile[(g + 1) * 130 + e] = v.y;
                sTile[(g + 2) * 130 + e] = v.z;
                sTile[(g + 3) * 130 + e] = v.w;
            }
        }
        __syncthreads();

        ull acc[4][8];
        zero_acc8(acc);
        mm8x8g<DNG>(sTile, w1, rg2, c0, acc);   // T = A @ W1
        __syncthreads();   // all reads of sA done before overwriting as sT

        // ssp(T + b1) -> sT transposed (STS.64 row-pairs)
        {
            float4 bA = __ldg((const float4*)(b1 + c0));
            float4 bB = __ldg((const float4*)(b1 + c0 + 4));
            float bv[8] = {bA.x, bA.y, bA.z, bA.w, bB.x, bB.y, bB.z, bB.w};
#pragma unroll
            for (int c = 0; c < 8; ++c) {
#pragma unroll
                for (int j = 0; j < 4; ++j) {
                    float2 v = unpack2(acc[j][c]);
                    *(float2*)(sTile + (c0 + c) * 130 + rg2 + 32 * j) =
                        make_float2(ssp_f(v.x + bv[c]), ssp_f(v.y + bv[c]));
                }
            }
        }
        __syncthreads();

        zero_acc8(acc);
        mm8x8g<DNF>(sTile, w2, rg2, c0, acc);   // Wmat = ssp(T) @ W2

        // epilogue: msg = (Wmat + b2)*C*h[src]; scatter-add to agg[dst].
        // Adjacent sorted edges usually share dst -> merge the two REDs into one.
        float4 bA = __ldg((const float4*)(b2 + c0));
        float4 bB = __ldg((const float4*)(b2 + c0 + 4));
        float bv[8] = {bA.x, bA.y, bA.z, bA.w, bB.x, bB.y, bB.z, bB.w};
#pragma unroll
        for (int j = 0; j < 4; ++j) {
            int el = rg2 + 32 * j;
            int gi = eg0 + el;
            float2 cv = __ldg((const float2*)(g_C + gi));
            int2 srcp = __ldg((const int2*)(g_src + gi));
            int2 dstp = __ldg((const int2*)(g_dst + gi));
            float2 vv[8];
#pragma unroll
            for (int c = 0; c < 8; ++c) vv[c] = unpack2(acc[j][c]);

            bool ok0 = (gi < cnt) && (cv.x != 0.0f);
            bool ok1 = (gi + 1 < cnt) && (cv.y != 0.0f);

            float m0[8], m1[8];
            if (ok0) {
                const float* hp = g_h + (size_t)srcp.x * DNF + c0;
                float4 h0 = ldcg4(hp);
                float4 h1 = ldcg4(hp + 4);
                float hh[8] = {h0.x, h0.y, h0.z, h0.w, h1.x, h1.y, h1.z, h1.w};
#pragma unroll
                for (int c = 0; c < 8; ++c) m0[c] = (vv[c].x + bv[c]) * cv.x * hh[c];
            }
            if (ok1) {
                const float* hp = g_h + (size_t)srcp.y * DNF + c0;
                float4 h0 = ldcg4(hp);
                float4 h1 = ldcg4(hp + 4);
                float hh[8] = {h0.x, h0.y, h0.z, h0.w, h1.x, h1.y, h1.z, h1.w};
#pragma unroll
                for (int c = 0; c < 8; ++c) m1[c] = (vv[c].y + bv[c]) * cv.y * hh[c];
            }

            if (ok0 && ok1 && dstp.x == dstp.y) {
                float* dp = g_agg + (size_t)dstp.x * DNF + c0;
                red_add_v4(dp, m0[0] + m1[0], m0[1] + m1[1], m0[2] + m1[2], m0[3] + m1[3]);
                red_add_v4(dp + 4, m0[4] + m1[4], m0[5] + m1[5], m0[6] + m1[6], m0[7] + m1[7]);
            } else {
                if (ok0) {
                    float* dp = g_agg + (size_t)dstp.x * DNF + c0;
                    red_add_v4(dp, m0[0], m0[1], m0[2], m0[3]);
                    red_add_v4(dp + 4, m0[4], m0[5], m0[6], m0[7]);
                }
                if (ok1) {
                    float* dp = g_agg + (size_t)dstp.y * DNF + c0;
                    red_add_v4(dp, m1[0], m1[1], m1[2], m1[3]);
                    red_add_v4(dp + 4, m1[4], m1[5], m1[6], m1[7]);
                }
            }
        }
    }
}

// -------- Kernel 3: out = ssp(agg@lin2_w + lin2_b) @ lin_w + lin_b --------
extern "C" __global__ void __launch_bounds__(512, 1)
k_out(const float* __restrict__ w2, const float* __restrict__ b2,
      const float* __restrict__ w3, const float* __restrict__ b3,
      float* __restrict__ out) {
    extern __shared__ float sm[];
    float* sW2 = sm;                  // 128*128 (lin2_w)
    float* sW3 = sW2 + DNF * DHID;    // 128*128 (lin_w)
    float* sA  = sW3 + DHID * DHID;   // 128*130 (aliased A then T)
    float* sB2 = sA + DNF * 130;      // 128
    float* sB3 = sB2 + 128;           // 128

    const int tid = threadIdx.x;
    const int rg = tid & 31, cg = tid >> 5;
    const int c0 = cg * 8;

    for (int i = tid; i < DNF * DHID / 4; i += 512)
        ((float4*)sW2)[i] = ((const float4*)w2)[i];
    for (int i = tid; i < DHID * DHID / 4; i += 512)
        ((float4*)sW3)[i] = ((const float4*)w3)[i];
    if (tid < DHID) { sB2[tid] = b2[tid]; sB3[tid] = b3[tid]; }

    const int ntiles = (NNODES + 127) / 128;
    for (int tile = blockIdx.x; tile < ntiles; tile += gridDim.x) {
        const int r0 = tile * 128;
        __syncthreads();
        {
            int e = tid >> 2, k0 = (tid & 3) << 5;
            int r = r0 + e;
            const float* src = g_agg + (size_t)r * DNF + k0;
#pragma unroll
            for (int i = 0; i < 8; ++i) {
                float4 v = (r < NNODES) ? ldcs4(src + 4 * i) : make_float4(0.f, 0.f, 0.f, 0.f);
                int k = k0 + 4 * i;
                sA[(k + 0) * 130 + e] = v.x;
                sA[(k + 1) * 130 + e] = v.y;
                sA[(k + 2) * 130 + e] = v.z;
                sA[(k + 3) * 130 + e] = v.w;
            }
        }
        __syncthreads();

        ull acc[4][4];
#pragma unroll
        for (int j = 0; j < 4; ++j)
#pragma unroll
            for (int p = 0; p < 4; ++p) acc[j][p] = 0ull;
        mm4x8<DNF>(sA, sW2, rg, c0, acc);
        __syncthreads();

#pragma unroll
        for (int p = 0; p < 4; ++p) {
            float bx = sB2[c0 + 2 * p], by = sB2[c0 + 2 * p + 1];
#pragma unroll
            for (int j = 0; j < 4; ++j) {
                float2 v = unpack2(acc[j][p]);
                int row = rg + 32 * j;
                sA[(c0 + 2 * p) * 130 + row] = ssp_f(v.x + bx);
                sA[(c0 + 2 * p + 1) * 130 + row] = ssp_f(v.y + by);
            }
        }
        __syncthreads();

#pragma unroll
        for (int j = 0; j < 4; ++j)
#pragma unroll
            for (int p = 0; p < 4; ++p) acc[j][p] = 0ull;
        mm4x8<DHID>(sA, sW3, rg, c0, acc);

#pragma unroll
        for (int j = 0; j < 4; ++j) {
            int r = r0 + rg + 32 * j;
            if (r < NNODES) {
                float2 v0 = unpack2(acc[j][0]), v1 = unpack2(acc[j][1]);
                float2 v2 = unpack2(acc[j][2]), v3 = unpack2(acc[j][3]);
                *(float4*)(out + (size_t)r * DHID + c0) =
                    make_float4(v0.x + sB3[c0 + 0], v0.y + sB3[c0 + 1],
                                v1.x + sB3[c0 + 2], v1.y + sB3[c0 + 3]);
                *(float4*)(out + (size_t)r * DHID + c0 + 4) =
                    make_float4(v2.x + sB3[c0 + 4], v2.y + sB3[c0 + 5],
                                v3.x + sB3[c0 + 6], v3.y + sB3[c0 + 7]);
            }
        }
    }
}

extern "C" void kernel_launch(void* const* d_in, const int* in_sizes, int n_in,
                              void* d_out, int out_size) {
    const float* x      = (const float*)d_in[0];
    const int*   ei     = (const int*)d_in[1];
    const float* elen   = (const float*)d_in[2];
    const float* eattr  = (const float*)d_in[3];
    const float* lin1_w = (const float*)d_in[4];
    const float* nn_w1  = (const float*)d_in[5];
    const float* nn_b1  = (const float*)d_in[6];
    const float* nn_w2  = (const float*)d_in[7];
    const float* nn_b2  = (const float*)d_in[8];
    const float* lin2_w = (const float*)d_in[9];
    const float* lin2_b = (const float*)d_in[10];
    const float* lin_w  = (const float*)d_in[11];
    const float* lin_b  = (const float*)d_in[12];
    float* out = (float*)d_out;

    size_t sm1 = (size_t)(DHID * 130) * 4;       // 66560
    size_t sm2 = (size_t)(DNF * 130) * 4;        // 66560
    size_t sm3 = (size_t)(DNF * DHID + DHID * DHID + DNF * 130 + 2 * 128) * 4;

    cudaFuncSetAttribute(k_proj_zero, cudaFuncAttributeMaxDynamicSharedMemorySize, (int)sm1);
    cudaFuncSetAttribute(k_edge, cudaFuncAttributeMaxDynamicSharedMemorySize, (int)sm2);
    cudaFuncSetAttribute(k_out, cudaFuncAttributeMaxDynamicSharedMemorySize, (int)sm3);

    k_proj_zero<<<304, 256, sm1>>>(x, lin1_w);   // h + zero agg + zero hist
    k_count<<<304, 256>>>(ei, elen);             // per-dst histogram
    k_scan<<<1, 1024>>>();                       // exclusive prefix -> g_off, g_cnt
    k_scatter<<<304, 256>>>(ei, elen);           // dst-sorted compaction
    k_edge<<<304, 256, sm2>>>(eattr, nn_w1, nn_b1, nn_w2, nn_b2);
    k_out<<<152, 512, sm3>>>(lin2_w, lin2_b, lin_w, lin_b, out);
}

// round 12
// speedup vs baseline: 1.0440x; 1.0354x over previous
#include <cuda_runtime.h>
#include <cstdint>

#define NNODES 50000
#define EEDGES 1600000
#define DHID 128
#define DNF 128
#define DNG 64
#define LN2 0.69314718055994530942f
#define FPI 3.14159265358979323846f

typedef unsigned long long ull;

// Scratch (static device arrays: allocation-free per harness rules)
__device__ float g_h[(size_t)NNODES * DNF];    // x @ lin1_w
__device__ float g_agg[(size_t)NNODES * DNF];  // segment_sum accumulator
__device__ int   g_cnt;                        // compacted edge count
__device__ int   g_hist[NNODES];               // per-dst edge count
__device__ int   g_off[NNODES];                // exclusive prefix (mutated by scatter)
__device__ int4  g_edge[EEDGES + 128];         // dst-sorted {eid, src, dst, C-bits} (padded)

// ---------------- helpers ----------------
__device__ __forceinline__ float ssp_f(float v) {
    return fmaxf(v, 0.0f) + __logf(1.0f + __expf(-fabsf(v))) - LN2;
}
__device__ __forceinline__ void red_add_v4(float* p, float a, float b, float c, float d) {
    asm volatile("red.global.add.v4.f32 [%0], {%1, %2, %3, %4};"
                 :: "l"(p), "f"(a), "f"(b), "f"(c), "f"(d) : "memory");
}
__device__ __forceinline__ ull pack2(float a) {
    ull r;
    asm("mov.b64 %0, {%1, %1};" : "=l"(r) : "f"(a));
    return r;
}
__device__ __forceinline__ float2 unpack2(ull v) {
    float2 f;
    asm("mov.b64 {%0, %1}, %2;" : "=f"(f.x), "=f"(f.y) : "l"(v));
    return f;
}
__device__ __forceinline__ void fma2(ull& d, ull a, ull b) {
    asm("fma.rn.f32x2 %0, %1, %2, %0;" : "+l"(d) : "l"(a), "l"(b));
}
__device__ __forceinline__ float4 ldcs4(const float* p) {
    float4 v;
    asm volatile("ld.global.cs.v4.f32 {%0,%1,%2,%3}, [%4];"
                 : "=f"(v.x), "=f"(v.y), "=f"(v.z), "=f"(v.w) : "l"(p));
    return v;
}
__device__ __forceinline__ float4 ldcg4(const float* p) {
    float4 v;
    asm volatile("ld.global.cg.v4.f32 {%0,%1,%2,%3}, [%4];"
                 : "=f"(v.x), "=f"(v.y), "=f"(v.z), "=f"(v.w) : "l"(p));
    return v;
}

// ---- 8x8 microkernel, 256 threads / 128x128 tile, B streamed from GLOBAL (L1-resident) ----
template <int K>
__device__ __forceinline__ void mm8x8g(const float* __restrict__ As,
                                       const float* __restrict__ Bg,
                                       int rg2, int c0, ull acc[4][8]) {
#pragma unroll 4
    for (int k = 0; k < K; ++k) {
        const float* ar = As + k * 130 + rg2;
        ull a0 = *(const ull*)(ar);
        ull a1 = *(const ull*)(ar + 32);
        ull a2 = *(const ull*)(ar + 64);
        ull a3 = *(const ull*)(ar + 96);
        const float4* bp = (const float4*)(Bg + k * 128 + c0);
        float4 b0 = __ldg(bp);
        float4 b1 = __ldg(bp + 1);
        ull bb[8] = {pack2(b0.x), pack2(b0.y), pack2(b0.z), pack2(b0.w),
                     pack2(b1.x), pack2(b1.y), pack2(b1.z), pack2(b1.w)};
#pragma unroll
        for (int c = 0; c < 8; ++c) {
            fma2(acc[0][c], a0, bb[c]);
            fma2(acc[1][c], a1, bb[c]);
            fma2(acc[2][c], a2, bb[c]);
            fma2(acc[3][c], a3, bb[c]);
        }
    }
}

__device__ __forceinline__ void zero_acc8(ull acc[4][8]) {
#pragma unroll
    for (int j = 0; j < 4; ++j)
#pragma unroll
        for (int c = 0; c < 8; ++c) acc[j][c] = 0ull;
}

// ---- 4x8 microkernel for k_out (512 threads, weights in smem) ----
template <int K>
__device__ __forceinline__ void mm4x8(const float* __restrict__ As,
                                      const float* __restrict__ Bs,
                                      int rg, int c0, ull acc[4][4]) {
#pragma unroll 4
    for (int k = 0; k < K; ++k) {
        const float* ar = As + k * 130 + rg;
        ull a0 = pack2(ar[0]);
        ull a1 = pack2(ar[32]);
        ull a2 = pack2(ar[64]);
        ull a3 = pack2(ar[96]);
        const float* br = Bs + k * 128 + c0;
        ulonglong2 b01 = *(const ulonglong2*)br;
        ulonglong2 b23 = *(const ulonglong2*)(br + 4);
        ull bb[4] = {b01.x, b01.y, b23.x, b23.y};
#pragma unroll
        for (int p = 0; p < 4; ++p) {
            fma2(acc[0][p], a0, bb[p]);
            fma2(acc[1][p], a1, bb[p]);
            fma2(acc[2][p], a2, bb[p]);
            fma2(acc[3][p], a3, bb[p]);
        }
    }
}

// ---------------- Kernel S1: per-dst histogram of valid edges ----------------
extern "C" __global__ void __launch_bounds__(256)
k_count(const int* __restrict__ ei, const float* __restrict__ elen) {
    const int stride = gridDim.x * blockDim.x;
    for (int i = blockIdx.x * blockDim.x + threadIdx.x; i < EEDGES; i += stride) {
        float L = elen[i];
        if (L <= 10.0f && L >= 0.0f)
            atomicAdd(&g_hist[ei[EEDGES + i]], 1);
    }
}

// ---------------- Kernel S2: exclusive prefix via warp-shuffle scan (1 CTA, fast) ----------
extern "C" __global__ void __launch_bounds__(1024)
k_scan() {
    __shared__ int wsum[32];
    const int tid = threadIdx.x;
    const int lane = tid & 31, wid = tid >> 5;
    int running = 0;
    for (int base = 0; base < NNODES; base += 1024) {
        int idx = base + tid;
        int v = (idx < NNODES) ? g_hist[idx] : 0;
        // inclusive warp scan
        int x = v;
#pragma unroll
        for (int o = 1; o < 32; o <<= 1) {
            int t = __shfl_up_sync(0xffffffffu, x, o);
            if (lane >= o) x += t;
        }
        if (lane == 31) wsum[wid] = x;
        __syncthreads();
        if (wid == 0) {
            int w = wsum[lane];
#pragma unroll
            for (int o = 1; o < 32; o <<= 1) {
                int t = __shfl_up_sync(0xffffffffu, w, o);
                if (lane >= o) w += t;
            }
            wsum[lane] = w;
        }
        __syncthreads();
        int woff = wid ? wsum[wid - 1] : 0;
        if (idx < NNODES) g_off[idx] = running + woff + x - v;   // exclusive
        running += wsum[31];
        __syncthreads();   // protect wsum for next chunk
    }
    if (tid == 0) g_cnt = running;
}

// ---------------- Kernel S3: scatter {eid,src,dst,C} as ONE 16B store ----------------
extern "C" __global__ void __launch_bounds__(256)
k_scatter(const int* __restrict__ ei, const float* __restrict__ elen) {
    const int stride = gridDim.x * blockDim.x;
    for (int i = blockIdx.x * blockDim.x + threadIdx.x; i < EEDGES; i += stride) {
        float L = elen[i];
        if (L <= 10.0f && L >= 0.0f) {
            int d = ei[EEDGES + i];
            int pos = atomicAdd(&g_off[d], 1);
            float C = 0.5f * (__cosf(L * (FPI / 10.0f)) + 1.0f);
            g_edge[pos] = make_int4(i, ei[i], d, __float_as_int(C));
        }
    }
}

// ---------------- Kernel 1: h = x @ lin1_w, zero g_agg + g_hist ----------------
extern "C" __global__ void __launch_bounds__(256, 2)
k_proj_zero(const float* __restrict__ x, const float* __restrict__ w1) {
    extern __shared__ float sm[];
    float* sX = sm;                 // 128*130 transposed tile
    const int tid = threadIdx.x;
    const int cg = tid >> 4, rg = tid & 15;
    const int c0 = cg * 8, rg2 = rg * 2;

    const int ntiles = (NNODES + 127) / 128;
    for (int tile = blockIdx.x; tile < ntiles; tile += gridDim.x) {
        const int r0 = tile * 128;
        __syncthreads();
        {
            int e = tid >> 1, k0 = (tid & 1) << 6;
            int r = r0 + e;
            if (r < NNODES) {
                const float* src = x + (size_t)r * DHID + k0;
#pragma unroll
                for (int i = 0; i < 16; ++i) {
                    float4 v = ldcs4(src + 4 * i);
                    int k = k0 + 4 * i;
                    sX[(k + 0) * 130 + e] = v.x;
                    sX[(k + 1) * 130 + e] = v.y;
                    sX[(k + 2) * 130 + e] = v.z;
                    sX[(k + 3) * 130 + e] = v.w;
                }
            }
        }
        __syncthreads();
        ull acc[4][8];
        zero_acc8(acc);
        mm8x8g<DHID>(sX, w1, rg2, c0, acc);
#pragma unroll
        for (int j = 0; j < 4; ++j) {
            int r = r0 + rg2 + 32 * j;
            float2 v0 = unpack2(acc[j][0]), v1 = unpack2(acc[j][1]);
            float2 v2 = unpack2(acc[j][2]), v3 = unpack2(acc[j][3]);
            float2 v4 = unpack2(acc[j][4]), v5 = unpack2(acc[j][5]);
            float2 v6 = unpack2(acc[j][6]), v7 = unpack2(acc[j][7]);
            if (r < NNODES) {
                *(float4*)(g_h + (size_t)r * DNF + c0) = make_float4(v0.x, v1.x, v2.x, v3.x);
                *(float4*)(g_h + (size_t)r * DNF + c0 + 4) = make_float4(v4.x, v5.x, v6.x, v7.x);
                *(float4*)(g_agg + (size_t)r * DNF + c0) = make_float4(0.f, 0.f, 0.f, 0.f);
                *(float4*)(g_agg + (size_t)r * DNF + c0 + 4) = make_float4(0.f, 0.f, 0.f, 0.f);
                if (cg == 0) g_hist[r] = 0;
            }
            if (r + 1 < NNODES) {
                *(float4*)(g_h + (size_t)(r + 1) * DNF + c0) = make_float4(v0.y, v1.y, v2.y, v3.y);
                *(float4*)(g_h + (size_t)(r + 1) * DNF + c0 + 4) = make_float4(v4.y, v5.y, v6.y, v7.y);
                *(float4*)(g_agg + (size_t)(r + 1) * DNF + c0) = make_float4(0.f, 0.f, 0.f, 0.f);
                *(float4*)(g_agg + (size_t)(r + 1) * DNF + c0 + 4) = make_float4(0.f, 0.f, 0.f, 0.f);
                if (cg == 0) g_hist[r + 1] = 0;
            }
        }
    }
}

// ---------------- Kernel 2: edge MLP + gather/scatter over dst-sorted edges ----------------
extern "C" __global__ void __launch_bounds__(256, 2)
k_edge(const float* __restrict__ edge_attr,
       const float* __restrict__ w1, const float* __restrict__ b1,
       const float* __restrict__ w2, const float* __restrict__ b2) {
    extern __shared__ float sm[];
    float* sTile = sm;     // union: sA (first 64 rows) / sT (128 rows), stride 130

    const int tid = threadIdx.x;
    const int cg = tid >> 4, rg = tid & 15;
    const int c0 = cg * 8, rg2 = rg * 2;

    const int cnt = g_cnt;
    const int ntiles = (cnt + 127) >> 7;
    for (int tile = blockIdx.x; tile < ntiles; tile += gridDim.x) {
        const int eg0 = tile << 7;
        __syncthreads();   // prev tile GEMM2 done with sT
        {
            int e = tid >> 1, g0 = (tid & 1) << 5;
            int gi = eg0 + e;
            int eid = (gi < cnt) ? __ldg(&g_edge[gi]).x : 0;
            const float* src = edge_attr + (size_t)eid * DNG + g0;
#pragma unroll
            for (int i = 0; i < 8; ++i) {
                float4 v = ldcs4(src + 4 * i);
                int g = g0 + 4 * i;
                sTile[(g + 0) * 130 + e] = v.x;
                sTile[(g + 1) * 130 + e] = v.y;
                sTile[(g + 2) * 130 + e] = v.z;
                sTile[(g + 3) * 130 + e] = v.w;
            }
        }
        __syncthreads();

        ull acc[4][8];
        zero_acc8(acc);
        mm8x8g<DNG>(sTile, w1, rg2, c0, acc);   // T = A @ W1
        __syncthreads();   // all reads of sA done before overwriting as sT

        // ssp(T + b1) -> sT transposed
        {
            float4 bA = __ldg((const float4*)(b1 + c0));
            float4 bB = __ldg((const float4*)(b1 + c0 + 4));
            float bv[8] = {bA.x, bA.y, bA.z, bA.w, bB.x, bB.y, bB.z, bB.w};
#pragma unroll
            for (int c = 0; c < 8; ++c) {
#pragma unroll
                for (int j = 0; j < 4; ++j) {
                    float2 v = unpack2(acc[j][c]);
                    *(float2*)(sTile + (c0 + c) * 130 + rg2 + 32 * j) =
                        make_float2(ssp_f(v.x + bv[c]), ssp_f(v.y + bv[c]));
                }
            }
        }
        __syncthreads();

        zero_acc8(acc);
        mm8x8g<DNF>(sTile, w2, rg2, c0, acc);   // Wmat = ssp(T) @ W2

        // epilogue: msg = (Wmat + b2)*C*h[src]; scatter-add to agg[dst].
        // Adjacent sorted edges usually share dst -> merge the two REDs into one.
        float4 bA = __ldg((const float4*)(b2 + c0));
        float4 bB = __ldg((const float4*)(b2 + c0 + 4));
        float bv[8] = {bA.x, bA.y, bA.z, bA.w, bB.x, bB.y, bB.z, bB.w};
#pragma unroll
        for (int j = 0; j < 4; ++j) {
            int el = rg2 + 32 * j;
            int gi = eg0 + el;
            int4 ed0 = __ldg(&g_edge[gi]);
            int4 ed1 = __ldg(&g_edge[gi + 1]);
            float cv0 = __int_as_float(ed0.w);
            float cv1 = __int_as_float(ed1.w);
            float2 vv[8];
#pragma unroll
            for (int c = 0; c < 8; ++c) vv[c] = unpack2(acc[j][c]);

            bool ok0 = (gi < cnt) && (cv0 != 0.0f);
            bool ok1 = (gi + 1 < cnt) && (cv1 != 0.0f);

            float m0[8], m1[8];
            if (ok0) {
                const float* hp = g_h + (size_t)ed0.y * DNF + c0;
                float4 h0 = ldcg4(hp);
                float4 h1 = ldcg4(hp + 4);
                float hh[8] = {h0.x, h0.y, h0.z, h0.w, h1.x, h1.y, h1.z, h1.w};
#pragma unroll
                for (int c = 0; c < 8; ++c) m0[c] = (vv[c].x + bv[c]) * cv0 * hh[c];
            }
            if (ok1) {
                const float* hp = g_h + (size_t)ed1.y * DNF + c0;
                float4 h0 = ldcg4(hp);
                float4 h1 = ldcg4(hp + 4);
                float hh[8] = {h0.x, h0.y, h0.z, h0.w, h1.x, h1.y, h1.z, h1.w};
#pragma unroll
                for (int c = 0; c < 8; ++c) m1[c] = (vv[c].y + bv[c]) * cv1 * hh[c];
            }

            if (ok0 && ok1 && ed0.z == ed1.z) {
                float* dp = g_agg + (size_t)ed0.z * DNF + c0;
                red_add_v4(dp, m0[0] + m1[0], m0[1] + m1[1], m0[2] + m1[2], m0[3] + m1[3]);
                red_add_v4(dp + 4, m0[4] + m1[4], m0[5] + m1[5], m0[6] + m1[6], m0[7] + m1[7]);
            } else {
                if (ok0) {
                    float* dp = g_agg + (size_t)ed0.z * DNF + c0;
                    red_add_v4(dp, m0[0], m0[1], m0[2], m0[3]);
                    red_add_v4(dp + 4, m0[4], m0[5], m0[6], m0[7]);
                }
                if (ok1) {
                    float* dp = g_agg + (size_t)ed1.z * DNF + c0;
                    red_add_v4(dp, m1[0], m1[1], m1[2], m1[3]);
                    red_add_v4(dp + 4, m1[4], m1[5], m1[6], m1[7]);
                }
            }
        }
    }
}

// -------- Kernel 3: out = ssp(agg@lin2_w + lin2_b) @ lin_w + lin_b --------
extern "C" __global__ void __launch_bounds__(512, 1)
k_out(const float* __restrict__ w2, const float* __restrict__ b2,
      const float* __restrict__ w3, const float* __restrict__ b3,
      float* __restrict__ out) {
    extern __shared__ float sm[];
    float* sW2 = sm;                  // 128*128 (lin2_w)
    float* sW3 = sW2 + DNF * DHID;    // 128*128 (lin_w)
    float* sA  = sW3 + DHID * DHID;   // 128*130 (aliased A then T)
    float* sB2 = sA + DNF * 130;      // 128
    float* sB3 = sB2 + 128;           // 128

    const int tid = threadIdx.x;
    const int rg = tid & 31, cg = tid >> 5;
    const int c0 = cg * 8;

    for (int i = tid; i < DNF * DHID / 4; i += 512)
        ((float4*)sW2)[i] = ((const float4*)w2)[i];
    for (int i = tid; i < DHID * DHID / 4; i += 512)
        ((float4*)sW3)[i] = ((const float4*)w3)[i];
    if (tid < DHID) { sB2[tid] = b2[tid]; sB3[tid] = b3[tid]; }

    const int ntiles = (NNODES + 127) / 128;
    for (int tile = blockIdx.x; tile < ntiles; tile += gridDim.x) {
        const int r0 = tile * 128;
        __syncthreads();
        {
            int e = tid >> 2, k0 = (tid & 3) << 5;
            int r = r0 + e;
            const float* src = g_agg + (size_t)r * DNF + k0;
#pragma unroll
            for (int i = 0; i < 8; ++i) {
                float4 v = (r < NNODES) ? ldcs4(src + 4 * i) : make_float4(0.f, 0.f, 0.f, 0.f);
                int k = k0 + 4 * i;
                sA[(k + 0) * 130 + e] = v.x;
                sA[(k + 1) * 130 + e] = v.y;
                sA[(k + 2) * 130 + e] = v.z;
                sA[(k + 3) * 130 + e] = v.w;
            }
        }
        __syncthreads();

        ull acc[4][4];
#pragma unroll
        for (int j = 0; j < 4; ++j)
#pragma unroll
            for (int p = 0; p < 4; ++p) acc[j][p] = 0ull;
        mm4x8<DNF>(sA, sW2, rg, c0, acc);
        __syncthreads();

#pragma unroll
        for (int p = 0; p < 4; ++p) {
            float bx = sB2[c0 + 2 * p], by = sB2[c0 + 2 * p + 1];
#pragma unroll
            for (int j = 0; j < 4; ++j) {
                float2 v = unpack2(acc[j][p]);
                int row = rg + 32 * j;
                sA[(c0 + 2 * p) * 130 + row] = ssp_f(v.x + bx);
                sA[(c0 + 2 * p + 1) * 130 + row] = ssp_f(v.y + by);
            }
        }
        __syncthreads();

#pragma unroll
        for (int j = 0; j < 4; ++j)
#pragma unroll
            for (int p = 0; p < 4; ++p) acc[j][p] = 0ull;
        mm4x8<DHID>(sA, sW3, rg, c0, acc);

#pragma unroll
        for (int j = 0; j < 4; ++j) {
            int r = r0 + rg + 32 * j;
            if (r < NNODES) {
                float2 v0 = unpack2(acc[j][0]), v1 = unpack2(acc[j][1]);
                float2 v2 = unpack2(acc[j][2]), v3 = unpack2(acc[j][3]);
                *(float4*)(out + (size_t)r * DHID + c0) =
                    make_float4(v0.x + sB3[c0 + 0], v0.y + sB3[c0 + 1],
                                v1.x + sB3[c0 + 2], v1.y + sB3[c0 + 3]);
                *(float4*)(out + (size_t)r * DHID + c0 + 4) =
                    make_float4(v2.x + sB3[c0 + 4], v2.y + sB3[c0 + 5],
                                v3.x + sB3[c0 + 6], v3.y + sB3[c0 + 7]);
            }
        }
    }
}

extern "C" void kernel_launch(void* const* d_in, const int* in_sizes, int n_in,
                              void* d_out, int out_size) {
    const float* x      = (const float*)d_in[0];
    const int*   ei     = (const int*)d_in[1];
    const float* elen   = (const float*)d_in[2];
    const float* eattr  = (const float*)d_in[3];
    const float* lin1_w = (const float*)d_in[4];
    const float* nn_w1  = (const float*)d_in[5];
    const float* nn_b1  = (const float*)d_in[6];
    const float* nn_w2  = (const float*)d_in[7];
    const float* nn_b2  = (const float*)d_in[8];
    const float* lin2_w = (const float*)d_in[9];
    const float* lin2_b = (const float*)d_in[10];
    const float* lin_w  = (const float*)d_in[11];
    const float* lin_b  = (const float*)d_in[12];
    float* out = (float*)d_out;

    size_t sm1 = (size_t)(DHID * 130) * 4;       // 66560
    size_t sm2 = (size_t)(DNF * 130) * 4;        // 66560
    size_t sm3 = (size_t)(DNF * DHID + DHID * DHID + DNF * 130 + 2 * 128) * 4;

    cudaFuncSetAttribute(k_proj_zero, cudaFuncAttributeMaxDynamicSharedMemorySize, (int)sm1);
    cudaFuncSetAttribute(k_edge, cudaFuncAttributeMaxDynamicSharedMemorySize, (int)sm2);
    cudaFuncSetAttribute(k_out, cudaFuncAttributeMaxDynamicSharedMemorySize, (int)sm3);

    k_proj_zero<<<304, 256, sm1>>>(x, lin1_w);   // h + zero agg + zero hist
    k_count<<<304, 256>>>(ei, elen);             // per-dst histogram
    k_scan<<<1, 1024>>>();                       // fast exclusive prefix -> g_off, g_cnt
    k_scatter<<<304, 256>>>(ei, elen);           // dst-sorted compaction (16B struct store)
    k_edge<<<304, 256, sm2>>>(eattr, nn_w1, nn_b1, nn_w2, nn_b2);
    k_out<<<152, 512, sm3>>>(lin2_w, lin2_b, lin_w, lin_b, out);
}

// round 13
// speedup vs baseline: 1.5977x; 1.5304x over previous
#include <cuda_runtime.h>
#include <cuda_bf16.h>
#include <cstdint>

#define NNODES 50000
#define EEDGES 1600000
#define DHID 128
#define DNF 128
#define DNG 64
#define LN2 0.69314718055994530942f
#define FPI 3.14159265358979323846f

typedef unsigned long long ull;
typedef unsigned int uint;

// Scratch (static device arrays: allocation-free per harness rules)
__device__ float g_h[(size_t)NNODES * DNF];    // x @ lin1_w
__device__ float g_agg[(size_t)NNODES * DNF];  // segment_sum accumulator
__device__ int   g_cnt;                        // compacted edge count
__device__ int   g_hist[NNODES];               // per-dst edge count
__device__ int   g_off[NNODES];                // exclusive prefix (mutated by scatter)
__device__ int4  g_edge[EEDGES + 128];         // dst-sorted {eid, src, dst, C-bits} (padded)

// ---------------- helpers ----------------
__device__ __forceinline__ float ssp_f(float v) {
    return fmaxf(v, 0.0f) + __logf(1.0f + __expf(-fabsf(v))) - LN2;
}
__device__ __forceinline__ void red_add_v4(float* p, float a, float b, float c, float d) {
    asm volatile("red.global.add.v4.f32 [%0], {%1, %2, %3, %4};"
                 :: "l"(p), "f"(a), "f"(b), "f"(c), "f"(d) : "memory");
}
__device__ __forceinline__ ull pack2(float a) {
    ull r;
    asm("mov.b64 %0, {%1, %1};" : "=l"(r) : "f"(a));
    return r;
}
__device__ __forceinline__ float2 unpack2(ull v) {
    float2 f;
    asm("mov.b64 {%0, %1}, %2;" : "=f"(f.x), "=f"(f.y) : "l"(v));
    return f;
}
__device__ __forceinline__ void fma2(ull& d, ull a, ull b) {
    asm("fma.rn.f32x2 %0, %1, %2, %0;" : "+l"(d) : "l"(a), "l"(b));
}
__device__ __forceinline__ float4 ldcs4(const float* p) {
    float4 v;
    asm volatile("ld.global.cs.v4.f32 {%0,%1,%2,%3}, [%4];"
                 : "=f"(v.x), "=f"(v.y), "=f"(v.z), "=f"(v.w) : "l"(p));
    return v;
}
__device__ __forceinline__ float4 ldcg4(const float* p) {
    float4 v;
    asm volatile("ld.global.cg.v4.f32 {%0,%1,%2,%3}, [%4];"
                 : "=f"(v.x), "=f"(v.y), "=f"(v.z), "=f"(v.w) : "l"(p));
    return v;
}

// bf16 mma.sync (sm_80-era PTX, valid on compute_103): D(16x8,f32) += A(16x16)B(16x8)
__device__ __forceinline__ void mma_bf16(float d[4], uint a0, uint a1, uint a2, uint a3,
                                         uint b0, uint b1) {
    asm volatile(
        "mma.sync.aligned.m16n8k16.row.col.f32.bf16.bf16.f32 "
        "{%0,%1,%2,%3}, {%4,%5,%6,%7}, {%8,%9}, {%0,%1,%2,%3};"
        : "+f"(d[0]), "+f"(d[1]), "+f"(d[2]), "+f"(d[3])
        : "r"(a0), "r"(a1), "r"(a2), "r"(a3), "r"(b0), "r"(b1));
}

// split (x,y) -> packed bf16 hi pair + lo pair
__device__ __forceinline__ void splitpair(float x, float y, uint& h, uint& l) {
    __nv_bfloat162 hh = __floats2bfloat162_rn(x, y);
    float2 hf = __bfloat1622float2(hh);
    __nv_bfloat162 ll = __floats2bfloat162_rn(x - hf.x, y - hf.y);
    h = *reinterpret_cast<uint*>(&hh);
    l = *reinterpret_cast<uint*>(&ll);
}

// ---- scalar microkernels for k_proj / k_out (unchanged, proven) ----
template <int K>
__device__ __forceinline__ void mm8x8g(const float* __restrict__ As,
                                       const float* __restrict__ Bg,
                                       int rg2, int c0, ull acc[4][8]) {
#pragma unroll 4
    for (int k = 0; k < K; ++k) {
        const float* ar = As + k * 130 + rg2;
        ull a0 = *(const ull*)(ar);
        ull a1 = *(const ull*)(ar + 32);
        ull a2 = *(const ull*)(ar + 64);
        ull a3 = *(const ull*)(ar + 96);
        const float4* bp = (const float4*)(Bg + k * 128 + c0);
        float4 b0 = __ldg(bp);
        float4 b1 = __ldg(bp + 1);
        ull bb[8] = {pack2(b0.x), pack2(b0.y), pack2(b0.z), pack2(b0.w),
                     pack2(b1.x), pack2(b1.y), pack2(b1.z), pack2(b1.w)};
#pragma unroll
        for (int c = 0; c < 8; ++c) {
            fma2(acc[0][c], a0, bb[c]);
            fma2(acc[1][c], a1, bb[c]);
            fma2(acc[2][c], a2, bb[c]);
            fma2(acc[3][c], a3, bb[c]);
        }
    }
}
template <int K>
__device__ __forceinline__ void mm4x8(const float* __restrict__ As,
                                      const float* __restrict__ Bs,
                                      int rg, int c0, ull acc[4][4]) {
#pragma unroll 4
    for (int k = 0; k < K; ++k) {
        const float* ar = As + k * 130 + rg;
        ull a0 = pack2(ar[0]);
        ull a1 = pack2(ar[32]);
        ull a2 = pack2(ar[64]);
        ull a3 = pack2(ar[96]);
        const float* br = Bs + k * 128 + c0;
        ulonglong2 b01 = *(const ulonglong2*)br;
        ulonglong2 b23 = *(const ulonglong2*)(br + 4);
        ull bb[4] = {b01.x, b01.y, b23.x, b23.y};
#pragma unroll
        for (int p = 0; p < 4; ++p) {
            fma2(acc[0][p], a0, bb[p]);
            fma2(acc[1][p], a1, bb[p]);
            fma2(acc[2][p], a2, bb[p]);
            fma2(acc[3][p], a3, bb[p]);
        }
    }
}

// ---------------- sort chain (unchanged from R12) ----------------
extern "C" __global__ void __launch_bounds__(256)
k_count(const int* __restrict__ ei, const float* __restrict__ elen) {
    const int stride = gridDim.x * blockDim.x;
    for (int i = blockIdx.x * blockDim.x + threadIdx.x; i < EEDGES; i += stride) {
        float L = elen[i];
        if (L <= 10.0f && L >= 0.0f)
            atomicAdd(&g_hist[ei[EEDGES + i]], 1);
    }
}

extern "C" __global__ void __launch_bounds__(1024)
k_scan() {
    __shared__ int wsum[32];
    const int tid = threadIdx.x;
    const int lane = tid & 31, wid = tid >> 5;
    int running = 0;
    for (int base = 0; base < NNODES; base += 1024) {
        int idx = base + tid;
        int v = (idx < NNODES) ? g_hist[idx] : 0;
        int x = v;
#pragma unroll
        for (int o = 1; o < 32; o <<= 1) {
            int t = __shfl_up_sync(0xffffffffu, x, o);
            if (lane >= o) x += t;
        }
        if (lane == 31) wsum[wid] = x;
        __syncthreads();
        if (wid == 0) {
            int w = wsum[lane];
#pragma unroll
            for (int o = 1; o < 32; o <<= 1) {
                int t = __shfl_up_sync(0xffffffffu, w, o);
                if (lane >= o) w += t;
            }
            wsum[lane] = w;
        }
        __syncthreads();
        int woff = wid ? wsum[wid - 1] : 0;
        if (idx < NNODES) g_off[idx] = running + woff + x - v;
        running += wsum[31];
        __syncthreads();
    }
    if (tid == 0) g_cnt = running;
}

extern "C" __global__ void __launch_bounds__(256)
k_scatter(const int* __restrict__ ei, const float* __restrict__ elen) {
    const int stride = gridDim.x * blockDim.x;
    for (int i = blockIdx.x * blockDim.x + threadIdx.x; i < EEDGES; i += stride) {
        float L = elen[i];
        if (L <= 10.0f && L >= 0.0f) {
            int d = ei[EEDGES + i];
            int pos = atomicAdd(&g_off[d], 1);
            float C = 0.5f * (__cosf(L * (FPI / 10.0f)) + 1.0f);
            g_edge[pos] = make_int4(i, ei[i], d, __float_as_int(C));
        }
    }
}

// ---------------- Kernel 1: h = x @ lin1_w, zero g_agg + g_hist (unchanged) ----------------
extern "C" __global__ void __launch_bounds__(256, 2)
k_proj_zero(const float* __restrict__ x, const float* __restrict__ w1) {
    extern __shared__ float smf[];
    float* sX = smf;
    const int tid = threadIdx.x;
    const int cg = tid >> 4, rg = tid & 15;
    const int c0 = cg * 8, rg2 = rg * 2;

    const int ntiles = (NNODES + 127) / 128;
    for (int tile = blockIdx.x; tile < ntiles; tile += gridDim.x) {
        const int r0 = tile * 128;
        __syncthreads();
        {
            int e = tid >> 1, k0 = (tid & 1) << 6;
            int r = r0 + e;
            if (r < NNODES) {
                const float* src = x + (size_t)r * DHID + k0;
#pragma unroll
                for (int i = 0; i < 16; ++i) {
                    float4 v = ldcs4(src + 4 * i);
                    int k = k0 + 4 * i;
                    sX[(k + 0) * 130 + e] = v.x;
                    sX[(k + 1) * 130 + e] = v.y;
                    sX[(k + 2) * 130 + e] = v.z;
                    sX[(k + 3) * 130 + e] = v.w;
                }
            }
        }
        __syncthreads();
        ull acc[4][8];
#pragma unroll
        for (int j = 0; j < 4; ++j)
#pragma unroll
            for (int c = 0; c < 8; ++c) acc[j][c] = 0ull;
        mm8x8g<DHID>(sX, w1, rg2, c0, acc);
#pragma unroll
        for (int j = 0; j < 4; ++j) {
            int r = r0 + rg2 + 32 * j;
            float2 v0 = unpack2(acc[j][0]), v1 = unpack2(acc[j][1]);
            float2 v2 = unpack2(acc[j][2]), v3 = unpack2(acc[j][3]);
            float2 v4 = unpack2(acc[j][4]), v5 = unpack2(acc[j][5]);
            float2 v6 = unpack2(acc[j][6]), v7 = unpack2(acc[j][7]);
            if (r < NNODES) {
                *(float4*)(g_h + (size_t)r * DNF + c0) = make_float4(v0.x, v1.x, v2.x, v3.x);
                *(float4*)(g_h + (size_t)r * DNF + c0 + 4) = make_float4(v4.x, v5.x, v6.x, v7.x);
                *(float4*)(g_agg + (size_t)r * DNF + c0) = make_float4(0.f, 0.f, 0.f, 0.f);
                *(float4*)(g_agg + (size_t)r * DNF + c0 + 4) = make_float4(0.f, 0.f, 0.f, 0.f);
                if (cg == 0) g_hist[r] = 0;
            }
            if (r + 1 < NNODES) {
                *(float4*)(g_h + (size_t)(r + 1) * DNF + c0) = make_float4(v0.y, v1.y, v2.y, v3.y);
                *(float4*)(g_h + (size_t)(r + 1) * DNF + c0 + 4) = make_float4(v4.y, v5.y, v6.y, v7.y);
                *(float4*)(g_agg + (size_t)(r + 1) * DNF + c0) = make_float4(0.f, 0.f, 0.f, 0.f);
                *(float4*)(g_agg + (size_t)(r + 1) * DNF + c0 + 4) = make_float4(0.f, 0.f, 0.f, 0.f);
                if (cg == 0) g_hist[r + 1] = 0;
            }
        }
    }
}

// ---------------- Kernel 2: HMMA (mma.sync bf16, 3-term split) edge MLP ----------------
// 512 thr, 1 CTA/SM. 16 warps: warp w -> rows (w&7)*16, col-half (w>>3)*64 (8 n-tiles of 8).
// Strides (bf16): K=64 arrays pad to 72, K=128 arrays pad to 136 (conflict-free frag LDS).
#define ST64 72
#define ST128 136
#define OFF_B1  0
#define OFF_B2  512
#define OFF_W1H 1024
#define OFF_W1L (OFF_W1H + 128 * ST64 * 2)
#define OFF_W2H (OFF_W1L + 128 * ST64 * 2)
#define OFF_W2L (OFF_W2H + 128 * ST128 * 2)
#define OFF_SAH (OFF_W2L + 128 * ST128 * 2)
#define OFF_SAL (OFF_SAH + 128 * ST64 * 2)
#define OFF_STH (OFF_SAL + 128 * ST64 * 2)
#define OFF_STL (OFF_STH + 128 * ST128 * 2)
#define OFF_STAGE OFF_STH                       // f32 128x132 union over sT region
#define SMEM_EDGE (OFF_STL + 128 * ST128 * 2)   // 214016 B

extern "C" __global__ void __launch_bounds__(512, 1)
k_edge(const float* __restrict__ edge_attr,
       const float* __restrict__ w1, const float* __restrict__ b1,
       const float* __restrict__ w2, const float* __restrict__ b2) {
    extern __shared__ __align__(16) char sm[];
    float* sB1 = (float*)(sm + OFF_B1);
    float* sB2 = (float*)(sm + OFF_B2);
    float* stage = (float*)(sm + OFF_STAGE);    // [128][132] f32

    const int tid = threadIdx.x;
    const int lane = tid & 31, wid = tid >> 5;
    const int g = lane >> 2, t = lane & 3;
    const int mw = (wid & 7) * 16;              // row strip
    const int nw = (wid >> 3) * 64;             // col half

    // ---- prologue: weights (transposed, hi/lo split) + biases ----
    for (int idx = tid; idx < DNG * DNF; idx += 512) {     // w1[k][f] -> sW1[f][k]
        int k = idx >> 7, f = idx & 127;
        float v = w1[idx];
        __nv_bfloat16 h = __float2bfloat16(v);
        __nv_bfloat16 l = __float2bfloat16(v - __bfloat162float(h));
        ((__nv_bfloat16*)(sm + OFF_W1H))[f * ST64 + k] = h;
        ((__nv_bfloat16*)(sm + OFF_W1L))[f * ST64 + k] = l;
    }
    for (int idx = tid; idx < DNF * DNF; idx += 512) {     // w2[f1][f2] -> sW2[f2][f1]
        int f1 = idx >> 7, f2 = idx & 127;
        float v = w2[idx];
        __nv_bfloat16 h = __float2bfloat16(v);
        __nv_bfloat16 l = __float2bfloat16(v - __bfloat162float(h));
        ((__nv_bfloat16*)(sm + OFF_W2H))[f2 * ST128 + f1] = h;
        ((__nv_bfloat16*)(sm + OFF_W2L))[f2 * ST128 + f1] = l;
    }
    if (tid < DNF) { sB1[tid] = b1[tid]; sB2[tid] = b2[tid]; }

    const int cnt = g_cnt;
    const int ntiles = (cnt + 127) >> 7;
    const int stride = gridDim.x;

    // A-tile loader: e = tid>>2, k0 = (tid&3)*16
    auto load_tile = [&](int tile) {
        int e = tid >> 2, k0 = (tid & 3) << 4;
        int gi = (tile << 7) + e;
        int eid = (gi < cnt) ? __ldg(&g_edge[gi]).x : 0;
        const float* src = edge_attr + (size_t)eid * DNG + k0;
        uint* dh = (uint*)(sm + OFF_SAH) + (e * ST64 + k0) / 2;
        uint* dl = (uint*)(sm + OFF_SAL) + (e * ST64 + k0) / 2;
#pragma unroll
        for (int i = 0; i < 4; ++i) {
            float4 v = ldcs4(src + 4 * i);
            uint h0, l0, h1, l1;
            splitpair(v.x, v.y, h0, l0);
            splitpair(v.z, v.w, h1, l1);
            dh[2 * i] = h0; dh[2 * i + 1] = h1;
            dl[2 * i] = l0; dl[2 * i + 1] = l1;
        }
    };

    int tile = blockIdx.x;
    if (tile < ntiles) load_tile(tile);
    __syncthreads();

    for (; tile < ntiles; tile += stride) {
        const int eg0 = tile << 7;

        // ---- GEMM1: D1 = Ah W1h + Al W1h + Ah W1l  (K=64) ----
        float d1[8][4];
#pragma unroll
        for (int nt = 0; nt < 8; ++nt)
#pragma unroll
            for (int q = 0; q < 4; ++q) d1[nt][q] = 0.0f;
#pragma unroll
        for (int kc = 0; kc < 4; ++kc) {
            const int kb = kc * 16 + 2 * t;
            const char* pah = sm + OFF_SAH;
            const char* pal = sm + OFF_SAL;
            uint ah0 = *(const uint*)(pah + ((mw + g) * ST64 + kb) * 2);
            uint ah1 = *(const uint*)(pah + ((mw + g + 8) * ST64 + kb) * 2);
            uint ah2 = *(const uint*)(pah + ((mw + g) * ST64 + kb + 8) * 2);
            uint ah3 = *(const uint*)(pah + ((mw + g + 8) * ST64 + kb + 8) * 2);
            uint al0 = *(const uint*)(pal + ((mw + g) * ST64 + kb) * 2);
            uint al1 = *(const uint*)(pal + ((mw + g + 8) * ST64 + kb) * 2);
            uint al2 = *(const uint*)(pal + ((mw + g) * ST64 + kb + 8) * 2);
            uint al3 = *(const uint*)(pal + ((mw + g + 8) * ST64 + kb + 8) * 2);
#pragma unroll
            for (int nt = 0; nt < 8; ++nt) {
                int n = nw + nt * 8 + g;
                uint bh0 = *(const uint*)(sm + OFF_W1H + (n * ST64 + kb) * 2);
                uint bh1 = *(const uint*)(sm + OFF_W1H + (n * ST64 + kb + 8) * 2);
                mma_bf16(d1[nt], ah0, ah1, ah2, ah3, bh0, bh1);
                mma_bf16(d1[nt], al0, al1, al2, al3, bh0, bh1);
                uint bl0 = *(const uint*)(sm + OFF_W1L + (n * ST64 + kb) * 2);
                uint bl1 = *(const uint*)(sm + OFF_W1L + (n * ST64 + kb + 8) * 2);
                mma_bf16(d1[nt], ah0, ah1, ah2, ah3, bl0, bl1);
            }
        }
        __syncthreads();   // sA reads done; previous epilogue done with stage (sT region)

        // ---- ssp(D1 + b1) -> sT hi/lo (bf16 pairs) ----
#pragma unroll
        for (int nt = 0; nt < 8; ++nt) {
            int c = nw + nt * 8 + 2 * t;
            float b0v = sB1[c], b1v = sB1[c + 1];
            uint h, l;
            splitpair(ssp_f(d1[nt][0] + b0v), ssp_f(d1[nt][1] + b1v), h, l);
            *(uint*)(sm + OFF_STH + ((mw + g) * ST128 + c) * 2) = h;
            *(uint*)(sm + OFF_STL + ((mw + g) * ST128 + c) * 2) = l;
            splitpair(ssp_f(d1[nt][2] + b0v), ssp_f(d1[nt][3] + b1v), h, l);
            *(uint*)(sm + OFF_STH + ((mw + g + 8) * ST128 + c) * 2) = h;
            *(uint*)(sm + OFF_STL + ((mw + g + 8) * ST128 + c) * 2) = l;
        }
        __syncthreads();   // sT ready

        // ---- GEMM2: D2 = Th W2h + Tl W2h + Th W2l  (K=128) ----
        float d2[8][4];
#pragma unroll
        for (int nt = 0; nt < 8; ++nt)
#pragma unroll
            for (int q = 0; q < 4; ++q) d2[nt][q] = 0.0f;
#pragma unroll
        for (int kc = 0; kc < 8; ++kc) {
            const int kb = kc * 16 + 2 * t;
            const char* pah = sm + OFF_STH;
            const char* pal = sm + OFF_STL;
            uint ah0 = *(const uint*)(pah + ((mw + g) * ST128 + kb) * 2);
            uint ah1 = *(const uint*)(pah + ((mw + g + 8) * ST128 + kb) * 2);
            uint ah2 = *(const uint*)(pah + ((mw + g) * ST128 + kb + 8) * 2);
            uint ah3 = *(const uint*)(pah + ((mw + g + 8) * ST128 + kb + 8) * 2);
            uint al0 = *(const uint*)(pal + ((mw + g) * ST128 + kb) * 2);
            uint al1 = *(const uint*)(pal + ((mw + g + 8) * ST128 + kb) * 2);
            uint al2 = *(const uint*)(pal + ((mw + g) * ST128 + kb + 8) * 2);
            uint al3 = *(const uint*)(pal + ((mw + g + 8) * ST128 + kb + 8) * 2);
#pragma unroll
            for (int nt = 0; nt < 8; ++nt) {
                int n = nw + nt * 8 + g;
                uint bh0 = *(const uint*)(sm + OFF_W2H + (n * ST128 + kb) * 2);
                uint bh1 = *(const uint*)(sm + OFF_W2H + (n * ST128 + kb + 8) * 2);
                mma_bf16(d2[nt], ah0, ah1, ah2, ah3, bh0, bh1);
                mma_bf16(d2[nt], al0, al1, al2, al3, bh0, bh1);
                uint bl0 = *(const uint*)(sm + OFF_W2L + (n * ST128 + kb) * 2);
                uint bl1 = *(const uint*)(sm + OFF_W2L + (n * ST128 + kb + 8) * 2);
                mma_bf16(d2[nt], ah0, ah1, ah2, ah3, bl0, bl1);
            }
        }
        __syncthreads();   // sT reads done -> stage (same region) may be overwritten

        // ---- stage D2 to smem (f32, stride 132) ----
#pragma unroll
        for (int nt = 0; nt < 8; ++nt) {
            int c = nw + nt * 8 + 2 * t;
            *(float2*)(stage + (mw + g) * 132 + c) = make_float2(d2[nt][0], d2[nt][1]);
            *(float2*)(stage + (mw + g + 8) * 132 + c) = make_float2(d2[nt][2], d2[nt][3]);
        }
        __syncthreads();   // stage ready

        // ---- epilogue: msg = (D2 + b2)*C*h[src]; RED to agg[dst] (dst-merge) ----
        {
            int pe = tid >> 3;                 // edge pair 0..63
            int c0 = (tid & 7) * 16;           // 16 cols
            int e0 = 2 * pe, e1 = 2 * pe + 1;
            int gi0 = eg0 + e0, gi1 = eg0 + e1;
            int4 ed0 = __ldg(&g_edge[gi0]);
            int4 ed1 = __ldg(&g_edge[gi1]);
            float cv0 = __int_as_float(ed0.w);
            float cv1 = __int_as_float(ed1.w);
            bool ok0 = (gi0 < cnt) && (cv0 != 0.0f);
            bool ok1 = (gi1 < cnt) && (cv1 != 0.0f);
            float m0[16], m1[16];
            if (ok0) {
                const float* hp = g_h + (size_t)ed0.y * DNF + c0;
#pragma unroll
                for (int q = 0; q < 4; ++q) {
                    float4 s = *(float4*)(stage + e0 * 132 + c0 + 4 * q);
                    float4 bb = *(float4*)(sB2 + c0 + 4 * q);
                    float4 hv = ldcg4(hp + 4 * q);
                    m0[4 * q + 0] = (s.x + bb.x) * cv0 * hv.x;
                    m0[4 * q + 1] = (s.y + bb.y) * cv0 * hv.y;
                    m0[4 * q + 2] = (s.z + bb.z) * cv0 * hv.z;
                    m0[4 * q + 3] = (s.w + bb.w) * cv0 * hv.w;
                }
            }
            if (ok1) {
                const float* hp = g_h + (size_t)ed1.y * DNF + c0;
#pragma unroll
                for (int q = 0; q < 4; ++q) {
                    float4 s = *(float4*)(stage + e1 * 132 + c0 + 4 * q);
                    float4 bb = *(float4*)(sB2 + c0 + 4 * q);
                    float4 hv = ldcg4(hp + 4 * q);
                    m1[4 * q + 0] = (s.x + bb.x) * cv1 * hv.x;
                    m1[4 * q + 1] = (s.y + bb.y) * cv1 * hv.y;
                    m1[4 * q + 2] = (s.z + bb.z) * cv1 * hv.z;
                    m1[4 * q + 3] = (s.w + bb.w) * cv1 * hv.w;
                }
            }
            if (ok0 && ok1 && ed0.z == ed1.z) {
                float* dp = g_agg + (size_t)ed0.z * DNF + c0;
#pragma unroll
                for (int q = 0; q < 4; ++q)
                    red_add_v4(dp + 4 * q, m0[4 * q] + m1[4 * q], m0[4 * q + 1] + m1[4 * q + 1],
                               m0[4 * q + 2] + m1[4 * q + 2], m0[4 * q + 3] + m1[4 * q + 3]);
            } else {
                if (ok0) {
                    float* dp = g_agg + (size_t)ed0.z * DNF + c0;
#pragma unroll
                    for (int q = 0; q < 4; ++q)
                        red_add_v4(dp + 4 * q, m0[4 * q], m0[4 * q + 1], m0[4 * q + 2], m0[4 * q + 3]);
                }
                if (ok1) {
                    float* dp = g_agg + (size_t)ed1.z * DNF + c0;
#pragma unroll
                    for (int q = 0; q < 4; ++q)
                        red_add_v4(dp + 4 * q, m1[4 * q], m1[4 * q + 1], m1[4 * q + 2], m1[4 * q + 3]);
                }
            }
        }
        // load next tile's A (sA free since GEMM1 done)
        if (tile + stride < ntiles) load_tile(tile + stride);
        __syncthreads();   // sA + stage consumption complete
    }
}

// -------- Kernel 3: out = ssp(agg@lin2_w + lin2_b) @ lin_w + lin_b (unchanged) --------
extern "C" __global__ void __launch_bounds__(512, 1)
k_out(const float* __restrict__ w2, const float* __restrict__ b2,
      const float* __restrict__ w3, const float* __restrict__ b3,
      float* __restrict__ out) {
    extern __shared__ float smf[];
    float* sW2 = smf;
    float* sW3 = sW2 + DNF * DHID;
    float* sA  = sW3 + DHID * DHID;
    float* sB2 = sA + DNF * 130;
    float* sB3 = sB2 + 128;

    const int tid = threadIdx.x;
    const int rg = tid & 31, cg = tid >> 5;
    const int c0 = cg * 8;

    for (int i = tid; i < DNF * DHID / 4; i += 512)
        ((float4*)sW2)[i] = ((const float4*)w2)[i];
    for (int i = tid; i < DHID * DHID / 4; i += 512)
        ((float4*)sW3)[i] = ((const float4*)w3)[i];
    if (tid < DHID) { sB2[tid] = b2[tid]; sB3[tid] = b3[tid]; }

    const int ntiles = (NNODES + 127) / 128;
    for (int tile = blockIdx.x; tile < ntiles; tile += gridDim.x) {
        const int r0 = tile * 128;
        __syncthreads();
        {
            int e = tid >> 2, k0 = (tid & 3) << 5;
            int r = r0 + e;
            const float* src = g_agg + (size_t)r * DNF + k0;
#pragma unroll
            for (int i = 0; i < 8; ++i) {
                float4 v = (r < NNODES) ? ldcs4(src + 4 * i) : make_float4(0.f, 0.f, 0.f, 0.f);
                int k = k0 + 4 * i;
                sA[(k + 0) * 130 + e] = v.x;
                sA[(k + 1) * 130 + e] = v.y;
                sA[(k + 2) * 130 + e] = v.z;
                sA[(k + 3) * 130 + e] = v.w;
            }
        }
        __syncthreads();

        ull acc[4][4];
#pragma unroll
        for (int j = 0; j < 4; ++j)
#pragma unroll
            for (int p = 0; p < 4; ++p) acc[j][p] = 0ull;
        mm4x8<DNF>(sA, sW2, rg, c0, acc);
        __syncthreads();

#pragma unroll
        for (int p = 0; p < 4; ++p) {
            float bx = sB2[c0 + 2 * p], by = sB2[c0 + 2 * p + 1];
#pragma unroll
            for (int j = 0; j < 4; ++j) {
                float2 v = unpack2(acc[j][p]);
                int row = rg + 32 * j;
                sA[(c0 + 2 * p) * 130 + row] = ssp_f(v.x + bx);
                sA[(c0 + 2 * p + 1) * 130 + row] = ssp_f(v.y + by);
            }
        }
        __syncthreads();

#pragma unroll
        for (int j = 0; j < 4; ++j)
#pragma unroll
            for (int p = 0; p < 4; ++p) acc[j][p] = 0ull;
        mm4x8<DHID>(sA, sW3, rg, c0, acc);

#pragma unroll
        for (int j = 0; j < 4; ++j) {
            int r = r0 + rg + 32 * j;
            if (r < NNODES) {
                float2 v0 = unpack2(acc[j][0]), v1 = unpack2(acc[j][1]);
                float2 v2 = unpack2(acc[j][2]), v3 = unpack2(acc[j][3]);
                *(float4*)(out + (size_t)r * DHID + c0) =
                    make_float4(v0.x + sB3[c0 + 0], v0.y + sB3[c0 + 1],
                                v1.x + sB3[c0 + 2], v1.y + sB3[c0 + 3]);
                *(float4*)(out + (size_t)r * DHID + c0 + 4) =
                    make_float4(v2.x + sB3[c0 + 4], v2.y + sB3[c0 + 5],
                                v3.x + sB3[c0 + 6], v3.y + sB3[c0 + 7]);
            }
        }
    }
}

extern "C" void kernel_launch(void* const* d_in, const int* in_sizes, int n_in,
                              void* d_out, int out_size) {
    const float* x      = (const float*)d_in[0];
    const int*   ei     = (const int*)d_in[1];
    const float* elen   = (const float*)d_in[2];
    const float* eattr  = (const float*)d_in[3];
    const float* lin1_w = (const float*)d_in[4];
    const float* nn_w1  = (const float*)d_in[5];
    const float* nn_b1  = (const float*)d_in[6];
    const float* nn_w2  = (const float*)d_in[7];
    const float* nn_b2  = (const float*)d_in[8];
    const float* lin2_w = (const float*)d_in[9];
    const float* lin2_b = (const float*)d_in[10];
    const float* lin_w  = (const float*)d_in[11];
    const float* lin_b  = (const float*)d_in[12];
    float* out = (float*)d_out;

    size_t sm1 = (size_t)(DHID * 130) * 4;
    size_t sm3 = (size_t)(DNF * DHID + DHID * DHID + DNF * 130 + 2 * 128) * 4;

    cudaFuncSetAttribute(k_proj_zero, cudaFuncAttributeMaxDynamicSharedMemorySize, (int)sm1);
    cudaFuncSetAttribute(k_edge, cudaFuncAttributeMaxDynamicSharedMemorySize, SMEM_EDGE);
    cudaFuncSetAttribute(k_out, cudaFuncAttributeMaxDynamicSharedMemorySize, (int)sm3);

    k_proj_zero<<<304, 256, sm1>>>(x, lin1_w);   // h + zero agg + zero hist
    k_count<<<304, 256>>>(ei, elen);
    k_scan<<<1, 1024>>>();
    k_scatter<<<304, 256>>>(ei, elen);
    k_edge<<<152, 512, SMEM_EDGE>>>(eattr, nn_w1, nn_b1, nn_w2, nn_b2);
    k_out<<<152, 512, sm3>>>(lin2_w, lin2_b, lin_w, lin_b, out);
}

// round 14
// speedup vs baseline: 1.6554x; 1.0361x over previous
#include <cuda_runtime.h>
#include <cuda_bf16.h>
#include <cstdint>

#define NNODES 50000
#define EEDGES 1600000
#define DHID 128
#define DNF 128
#define DNG 64
#define LN2 0.69314718055994530942f
#define FPI 3.14159265358979323846f

typedef unsigned long long ull;
typedef unsigned int uint;

// Scratch (static device arrays: allocation-free per harness rules)
__device__ float g_h[(size_t)NNODES * DNF];    // x @ lin1_w
__device__ float g_agg[(size_t)NNODES * DNF];  // segment_sum accumulator
__device__ int   g_cnt;                        // compacted edge count
__device__ int   g_hist[NNODES];               // per-dst edge count
__device__ int   g_off[NNODES];                // exclusive prefix (mutated by scatter)
__device__ int4  g_edge[EEDGES + 128];         // dst-sorted {eid, src, dst, C-bits} (padded)

// ---------------- helpers ----------------
__device__ __forceinline__ float ssp_f(float v) {
    return fmaxf(v, 0.0f) + __logf(1.0f + __expf(-fabsf(v))) - LN2;
}
__device__ __forceinline__ void red_add_v4(float* p, float a, float b, float c, float d) {
    asm volatile("red.global.add.v4.f32 [%0], {%1, %2, %3, %4};"
                 :: "l"(p), "f"(a), "f"(b), "f"(c), "f"(d) : "memory");
}
__device__ __forceinline__ ull pack2(float a) {
    ull r;
    asm("mov.b64 %0, {%1, %1};" : "=l"(r) : "f"(a));
    return r;
}
__device__ __forceinline__ float2 unpack2(ull v) {
    float2 f;
    asm("mov.b64 {%0, %1}, %2;" : "=f"(f.x), "=f"(f.y) : "l"(v));
    return f;
}
__device__ __forceinline__ void fma2(ull& d, ull a, ull b) {
    asm("fma.rn.f32x2 %0, %1, %2, %0;" : "+l"(d) : "l"(a), "l"(b));
}
__device__ __forceinline__ float4 ldcs4(const float* p) {
    float4 v;
    asm volatile("ld.global.cs.v4.f32 {%0,%1,%2,%3}, [%4];"
                 : "=f"(v.x), "=f"(v.y), "=f"(v.z), "=f"(v.w) : "l"(p));
    return v;
}
__device__ __forceinline__ float4 ldcg4(const float* p) {
    float4 v;
    asm volatile("ld.global.cg.v4.f32 {%0,%1,%2,%3}, [%4];"
                 : "=f"(v.x), "=f"(v.y), "=f"(v.z), "=f"(v.w) : "l"(p));
    return v;
}

// bf16 mma.sync: D(16x8,f32) += A(16x16)B(16x8)
__device__ __forceinline__ void mma_bf16(float d[4], uint a0, uint a1, uint a2, uint a3,
                                         uint b0, uint b1) {
    asm volatile(
        "mma.sync.aligned.m16n8k16.row.col.f32.bf16.bf16.f32 "
        "{%0,%1,%2,%3}, {%4,%5,%6,%7}, {%8,%9}, {%0,%1,%2,%3};"
        : "+f"(d[0]), "+f"(d[1]), "+f"(d[2]), "+f"(d[3])
        : "r"(a0), "r"(a1), "r"(a2), "r"(a3), "r"(b0), "r"(b1));
}
// ldmatrix x4 (A fragments for m16n8k16 row-major)
__device__ __forceinline__ void ldsm4(uint& r0, uint& r1, uint& r2, uint& r3, uint addr) {
    asm volatile("ldmatrix.sync.aligned.m8n8.x4.shared.b16 {%0,%1,%2,%3}, [%4];"
                 : "=r"(r0), "=r"(r1), "=r"(r2), "=r"(r3) : "r"(addr));
}

// split (x,y) -> packed bf16 hi pair + lo pair
__device__ __forceinline__ void splitpair(float x, float y, uint& h, uint& l) {
    __nv_bfloat162 hh = __floats2bfloat162_rn(x, y);
    float2 hf = __bfloat1622float2(hh);
    __nv_bfloat162 ll = __floats2bfloat162_rn(x - hf.x, y - hf.y);
    h = *reinterpret_cast<uint*>(&hh);
    l = *reinterpret_cast<uint*>(&ll);
}

// ---- scalar microkernels for k_proj / k_out ----
template <int K>
__device__ __forceinline__ void mm8x8g(const float* __restrict__ As,
                                       const float* __restrict__ Bg,
                                       int rg2, int c0, ull acc[4][8]) {
#pragma unroll 4
    for (int k = 0; k < K; ++k) {
        const float* ar = As + k * 130 + rg2;
        ull a0 = *(const ull*)(ar);
        ull a1 = *(const ull*)(ar + 32);
        ull a2 = *(const ull*)(ar + 64);
        ull a3 = *(const ull*)(ar + 96);
        const float4* bp = (const float4*)(Bg + k * 128 + c0);
        float4 b0 = __ldg(bp);
        float4 b1 = __ldg(bp + 1);
        ull bb[8] = {pack2(b0.x), pack2(b0.y), pack2(b0.z), pack2(b0.w),
                     pack2(b1.x), pack2(b1.y), pack2(b1.z), pack2(b1.w)};
#pragma unroll
        for (int c = 0; c < 8; ++c) {
            fma2(acc[0][c], a0, bb[c]);
            fma2(acc[1][c], a1, bb[c]);
            fma2(acc[2][c], a2, bb[c]);
            fma2(acc[3][c], a3, bb[c]);
        }
    }
}
template <int K>
__device__ __forceinline__ void mm4x8(const float* __restrict__ As,
                                      const float* __restrict__ Bs,
                                      int rg, int c0, ull acc[4][4]) {
#pragma unroll 4
    for (int k = 0; k < K; ++k) {
        const float* ar = As + k * 130 + rg;
        ull a0 = pack2(ar[0]);
        ull a1 = pack2(ar[32]);
        ull a2 = pack2(ar[64]);
        ull a3 = pack2(ar[96]);
        const float* br = Bs + k * 128 + c0;
        ulonglong2 b01 = *(const ulonglong2*)br;
        ulonglong2 b23 = *(const ulonglong2*)(br + 4);
        ull bb[4] = {b01.x, b01.y, b23.x, b23.y};
#pragma unroll
        for (int p = 0; p < 4; ++p) {
            fma2(acc[0][p], a0, bb[p]);
            fma2(acc[1][p], a1, bb[p]);
            fma2(acc[2][p], a2, bb[p]);
            fma2(acc[3][p], a3, bb[p]);
        }
    }
}

// ---------------- sort chain ----------------
extern "C" __global__ void __launch_bounds__(256)
k_count(const int* __restrict__ ei, const float* __restrict__ elen) {
    const int stride = gridDim.x * blockDim.x;
    for (int i = blockIdx.x * blockDim.x + threadIdx.x; i < EEDGES; i += stride) {
        float L = elen[i];
        if (L <= 10.0f && L >= 0.0f)
            atomicAdd(&g_hist[ei[EEDGES + i]], 1);
    }
}

extern "C" __global__ void __launch_bounds__(1024)
k_scan() {
    __shared__ int wsum[32];
    const int tid = threadIdx.x;
    const int lane = tid & 31, wid = tid >> 5;
    int running = 0;
    for (int base = 0; base < NNODES; base += 1024) {
        int idx = base + tid;
        int v = (idx < NNODES) ? g_hist[idx] : 0;
        int x = v;
#pragma unroll
        for (int o = 1; o < 32; o <<= 1) {
            int t = __shfl_up_sync(0xffffffffu, x, o);
            if (lane >= o) x += t;
        }
        if (lane == 31) wsum[wid] = x;
        __syncthreads();
        if (wid == 0) {
            int w = wsum[lane];
#pragma unroll
            for (int o = 1; o < 32; o <<= 1) {
                int t = __shfl_up_sync(0xffffffffu, w, o);
                if (lane >= o) w += t;
            }
            wsum[lane] = w;
        }
        __syncthreads();
        int woff = wid ? wsum[wid - 1] : 0;
        if (idx < NNODES) g_off[idx] = running + woff + x - v;
        running += wsum[31];
        __syncthreads();
    }
    if (tid == 0) g_cnt = running;
}

extern "C" __global__ void __launch_bounds__(256)
k_scatter(const int* __restrict__ ei, const float* __restrict__ elen) {
    const int stride = gridDim.x * blockDim.x;
    for (int i = blockIdx.x * blockDim.x + threadIdx.x; i < EEDGES; i += stride) {
        float L = elen[i];
        if (L <= 10.0f && L >= 0.0f) {
            int d = ei[EEDGES + i];
            int pos = atomicAdd(&g_off[d], 1);
            float C = 0.5f * (__cosf(L * (FPI / 10.0f)) + 1.0f);
            g_edge[pos] = make_int4(i, ei[i], d, __float_as_int(C));
        }
    }
}

// dummy so ncu's -s5 window (6th launch) lands on k_edge
extern "C" __global__ void k_nop() {}

// ---------------- Kernel 1: h = x @ lin1_w, zero g_agg + g_hist ----------------
extern "C" __global__ void __launch_bounds__(256, 2)
k_proj_zero(const float* __restrict__ x, const float* __restrict__ w1) {
    extern __shared__ float smf[];
    float* sX = smf;
    const int tid = threadIdx.x;
    const int cg = tid >> 4, rg = tid & 15;
    const int c0 = cg * 8, rg2 = rg * 2;

    const int ntiles = (NNODES + 127) / 128;
    for (int tile = blockIdx.x; tile < ntiles; tile += gridDim.x) {
        const int r0 = tile * 128;
        __syncthreads();
        {
            int e = tid >> 1, k0 = (tid & 1) << 6;
            int r = r0 + e;
            if (r < NNODES) {
                const float* src = x + (size_t)r * DHID + k0;
#pragma unroll
                for (int i = 0; i < 16; ++i) {
                    float4 v = ldcs4(src + 4 * i);
                    int k = k0 + 4 * i;
                    sX[(k + 0) * 130 + e] = v.x;
                    sX[(k + 1) * 130 + e] = v.y;
                    sX[(k + 2) * 130 + e] = v.z;
                    sX[(k + 3) * 130 + e] = v.w;
                }
            }
        }
        __syncthreads();
        ull acc[4][8];
#pragma unroll
        for (int j = 0; j < 4; ++j)
#pragma unroll
            for (int c = 0; c < 8; ++c) acc[j][c] = 0ull;
        mm8x8g<DHID>(sX, w1, rg2, c0, acc);
#pragma unroll
        for (int j = 0; j < 4; ++j) {
            int r = r0 + rg2 + 32 * j;
            float2 v0 = unpack2(acc[j][0]), v1 = unpack2(acc[j][1]);
            float2 v2 = unpack2(acc[j][2]), v3 = unpack2(acc[j][3]);
            float2 v4 = unpack2(acc[j][4]), v5 = unpack2(acc[j][5]);
            float2 v6 = unpack2(acc[j][6]), v7 = unpack2(acc[j][7]);
            if (r < NNODES) {
                *(float4*)(g_h + (size_t)r * DNF + c0) = make_float4(v0.x, v1.x, v2.x, v3.x);
                *(float4*)(g_h + (size_t)r * DNF + c0 + 4) = make_float4(v4.x, v5.x, v6.x, v7.x);
                *(float4*)(g_agg + (size_t)r * DNF + c0) = make_float4(0.f, 0.f, 0.f, 0.f);
                *(float4*)(g_agg + (size_t)r * DNF + c0 + 4) = make_float4(0.f, 0.f, 0.f, 0.f);
                if (cg == 0) g_hist[r] = 0;
            }
            if (r + 1 < NNODES) {
                *(float4*)(g_h + (size_t)(r + 1) * DNF + c0) = make_float4(v0.y, v1.y, v2.y, v3.y);
                *(float4*)(g_h + (size_t)(r + 1) * DNF + c0 + 4) = make_float4(v4.y, v5.y, v6.y, v7.y);
                *(float4*)(g_agg + (size_t)(r + 1) * DNF + c0) = make_float4(0.f, 0.f, 0.f, 0.f);
                *(float4*)(g_agg + (size_t)(r + 1) * DNF + c0 + 4) = make_float4(0.f, 0.f, 0.f, 0.f);
                if (cg == 0) g_hist[r + 1] = 0;
            }
        }
    }
}

// ---------------- Kernel 2: HMMA edge MLP (ldmatrix frags + pipelined A-load) ----------------
#define ST64 72
#define ST128 136
#define OFF_B1  0
#define OFF_B2  512
#define OFF_W1H 1024
#define OFF_W1L (OFF_W1H + 128 * ST64 * 2)
#define OFF_W2H (OFF_W1L + 128 * ST64 * 2)
#define OFF_W2L (OFF_W2H + 128 * ST128 * 2)
#define OFF_SAH (OFF_W2L + 128 * ST128 * 2)
#define OFF_SAL (OFF_SAH + 128 * ST64 * 2)
#define OFF_STH (OFF_SAL + 128 * ST64 * 2)
#define OFF_STL (OFF_STH + 128 * ST128 * 2)
#define OFF_STAGE OFF_STH                       // f32 128x132 union over sT region
#define SMEM_EDGE (OFF_STL + 128 * ST128 * 2)   // 214016 B

extern "C" __global__ void __launch_bounds__(512, 1)
k_edge(const float* __restrict__ edge_attr,
       const float* __restrict__ w1, const float* __restrict__ b1,
       const float* __restrict__ w2, const float* __restrict__ b2) {
    extern __shared__ __align__(16) char sm[];
    float* sB1 = (float*)(sm + OFF_B1);
    float* sB2 = (float*)(sm + OFF_B2);
    float* stage = (float*)(sm + OFF_STAGE);    // [128][132] f32

    const int tid = threadIdx.x;
    const int lane = tid & 31, wid = tid >> 5;
    const int g = lane >> 2, t = lane & 3;
    const int mw = (wid & 7) * 16;              // row strip
    const int nw = (wid >> 3) * 64;             // col half

    // ldmatrix lane addressing for A/T fragments
    const int arow = mw + (lane & 7) + ((lane >> 3) & 1) * 8;
    const int acol = ((lane >> 4) & 1) * 8;
    const uint sbase = (uint)__cvta_generic_to_shared(sm);
    const uint aSAH = sbase + OFF_SAH + (uint)((arow * ST64 + acol) * 2);
    const uint aSAL = sbase + OFF_SAL + (uint)((arow * ST64 + acol) * 2);
    const uint aSTH = sbase + OFF_STH + (uint)((arow * ST128 + acol) * 2);
    const uint aSTL = sbase + OFF_STL + (uint)((arow * ST128 + acol) * 2);

    // ---- prologue: weights (transposed, hi/lo split) + biases ----
    for (int idx = tid; idx < DNG * DNF; idx += 512) {     // w1[k][f] -> sW1[f][k]
        int k = idx >> 7, f = idx & 127;
        float v = w1[idx];
        __nv_bfloat16 h = __float2bfloat16(v);
        __nv_bfloat16 l = __float2bfloat16(v - __bfloat162float(h));
        ((__nv_bfloat16*)(sm + OFF_W1H))[f * ST64 + k] = h;
        ((__nv_bfloat16*)(sm + OFF_W1L))[f * ST64 + k] = l;
    }
    for (int idx = tid; idx < DNF * DNF; idx += 512) {     // w2[f1][f2] -> sW2[f2][f1]
        int f1 = idx >> 7, f2 = idx & 127;
        float v = w2[idx];
        __nv_bfloat16 h = __float2bfloat16(v);
        __nv_bfloat16 l = __float2bfloat16(v - __bfloat162float(h));
        ((__nv_bfloat16*)(sm + OFF_W2H))[f2 * ST128 + f1] = h;
        ((__nv_bfloat16*)(sm + OFF_W2L))[f2 * ST128 + f1] = l;
    }
    if (tid < DNF) { sB1[tid] = b1[tid]; sB2[tid] = b2[tid]; }

    const int cnt = g_cnt;
    const int ntiles = (cnt + 127) >> 7;
    const int stride = gridDim.x;

    const int le = tid >> 2, lk0 = (tid & 3) << 4;   // A-load mapping

    auto ldg_tile = [&](int tile, float4 pf[4]) {
        int gi = (tile << 7) + le;
        int eid = (gi < cnt) ? __ldg(&g_edge[gi]).x : 0;
        const float* src = edge_attr + (size_t)eid * DNG + lk0;
#pragma unroll
        for (int i = 0; i < 4; ++i) pf[i] = ldcs4(src + 4 * i);
    };
    auto sts_tile = [&](const float4 pf[4]) {
        uint* dh = (uint*)(sm + OFF_SAH) + (le * ST64 + lk0) / 2;
        uint* dl = (uint*)(sm + OFF_SAL) + (le * ST64 + lk0) / 2;
#pragma unroll
        for (int i = 0; i < 4; ++i) {
            uint h0, l0, h1, l1;
            splitpair(pf[i].x, pf[i].y, h0, l0);
            splitpair(pf[i].z, pf[i].w, h1, l1);
            dh[2 * i] = h0; dh[2 * i + 1] = h1;
            dl[2 * i] = l0; dl[2 * i + 1] = l1;
        }
    };

    int tile = blockIdx.x;
    if (tile < ntiles) {
        float4 pf[4];
        ldg_tile(tile, pf);
        sts_tile(pf);
    }
    __syncthreads();

    for (; tile < ntiles; tile += stride) {
        const int eg0 = tile << 7;

        // ---- GEMM1: D1 = Ah W1h + Al W1h + Ah W1l  (K=64) ----
        float d1[8][4];
#pragma unroll
        for (int nt = 0; nt < 8; ++nt)
#pragma unroll
            for (int q = 0; q < 4; ++q) d1[nt][q] = 0.0f;
#pragma unroll
        for (int kc = 0; kc < 4; ++kc) {
            uint ah0, ah1, ah2, ah3, al0, al1, al2, al3;
            ldsm4(ah0, ah1, ah2, ah3, aSAH + kc * 32);
            ldsm4(al0, al1, al2, al3, aSAL + kc * 32);
            const int kb = kc * 16 + 2 * t;
#pragma unroll
            for (int nt = 0; nt < 8; ++nt) {
                int n = nw + nt * 8 + g;
                uint bh0 = *(const uint*)(sm + OFF_W1H + (n * ST64 + kb) * 2);
                uint bh1 = *(const uint*)(sm + OFF_W1H + (n * ST64 + kb + 8) * 2);
                mma_bf16(d1[nt], ah0, ah1, ah2, ah3, bh0, bh1);
                mma_bf16(d1[nt], al0, al1, al2, al3, bh0, bh1);
                uint bl0 = *(const uint*)(sm + OFF_W1L + (n * ST64 + kb) * 2);
                uint bl1 = *(const uint*)(sm + OFF_W1L + (n * ST64 + kb + 8) * 2);
                mma_bf16(d1[nt], ah0, ah1, ah2, ah3, bl0, bl1);
            }
        }
        __syncthreads();   // sA reads done (prev epilogue done via program order)

        // ---- prefetch next tile's A from global (latency hidden by ssp + GEMM2) ----
        const int tnext = tile + stride;
        const bool have = tnext < ntiles;
        float4 pf[4];
        if (have) ldg_tile(tnext, pf);

        // ---- ssp(D1 + b1) -> sT hi/lo ----
#pragma unroll
        for (int nt = 0; nt < 8; ++nt) {
            int c = nw + nt * 8 + 2 * t;
            float b0v = sB1[c], b1v = sB1[c + 1];
            uint h, l;
            splitpair(ssp_f(d1[nt][0] + b0v), ssp_f(d1[nt][1] + b1v), h, l);
            *(uint*)(sm + OFF_STH + ((mw + g) * ST128 + c) * 2) = h;
            *(uint*)(sm + OFF_STL + ((mw + g) * ST128 + c) * 2) = l;
            splitpair(ssp_f(d1[nt][2] + b0v), ssp_f(d1[nt][3] + b1v), h, l);
            *(uint*)(sm + OFF_STH + ((mw + g + 8) * ST128 + c) * 2) = h;
            *(uint*)(sm + OFF_STL + ((mw + g + 8) * ST128 + c) * 2) = l;
        }
        __syncthreads();   // sT ready

        // ---- GEMM2: D2 = Th W2h + Tl W2h + Th W2l  (K=128) ----
        float d2[8][4];
#pragma unroll
        for (int nt = 0; nt < 8; ++nt)
#pragma unroll
            for (int q = 0; q < 4; ++q) d2[nt][q] = 0.0f;
#pragma unroll
        for (int kc = 0; kc < 8; ++kc) {
            uint ah0, ah1, ah2, ah3, al0, al1, al2, al3;
            ldsm4(ah0, ah1, ah2, ah3, aSTH + kc * 32);
            ldsm4(al0, al1, al2, al3, aSTL + kc * 32);
            const int kb = kc * 16 + 2 * t;
#pragma unroll
            for (int nt = 0; nt < 8; ++nt) {
                int n = nw + nt * 8 + g;
                uint bh0 = *(const uint*)(sm + OFF_W2H + (n * ST128 + kb) * 2);
                uint bh1 = *(const uint*)(sm + OFF_W2H + (n * ST128 + kb + 8) * 2);
                mma_bf16(d2[nt], ah0, ah1, ah2, ah3, bh0, bh1);
                mma_bf16(d2[nt], al0, al1, al2, al3, bh0, bh1);
                uint bl0 = *(const uint*)(sm + OFF_W2L + (n * ST128 + kb) * 2);
                uint bl1 = *(const uint*)(sm + OFF_W2L + (n * ST128 + kb + 8) * 2);
                mma_bf16(d2[nt], ah0, ah1, ah2, ah3, bl0, bl1);
            }
        }
        __syncthreads();   // sT reads done -> stage writable; sA writable

        // ---- stage D2 to smem + store prefetched A ----
#pragma unroll
        for (int nt = 0; nt < 8; ++nt) {
            int c = nw + nt * 8 + 2 * t;
            *(float2*)(stage + (mw + g) * 132 + c) = make_float2(d2[nt][0], d2[nt][1]);
            *(float2*)(stage + (mw + g + 8) * 132 + c) = make_float2(d2[nt][2], d2[nt][3]);
        }
        if (have) sts_tile(pf);
        __syncthreads();   // stage + sA ready

        // ---- epilogue: msg = (D2 + b2)*C*h[src]; RED to agg[dst] (dst-merge) ----
        {
            int pe = tid >> 3;                 // edge pair 0..63
            int c0 = (tid & 7) * 16;           // 16 cols
            int e0 = 2 * pe, e1 = 2 * pe + 1;
            int gi0 = eg0 + e0, gi1 = eg0 + e1;
            int4 ed0 = __ldg(&g_edge[gi0]);
            int4 ed1 = __ldg(&g_edge[gi1]);
            float cv0 = __int_as_float(ed0.w);
            float cv1 = __int_as_float(ed1.w);
            bool ok0 = (gi0 < cnt) && (cv0 != 0.0f);
            bool ok1 = (gi1 < cnt) && (cv1 != 0.0f);
            float m0[16], m1[16];
            if (ok0) {
                const float* hp = g_h + (size_t)ed0.y * DNF + c0;
#pragma unroll
                for (int q = 0; q < 4; ++q) {
                    float4 s = *(float4*)(stage + e0 * 132 + c0 + 4 * q);
                    float4 bb = *(float4*)(sB2 + c0 + 4 * q);
                    float4 hv = ldcg4(hp + 4 * q);
                    m0[4 * q + 0] = (s.x + bb.x) * cv0 * hv.x;
                    m0[4 * q + 1] = (s.y + bb.y) * cv0 * hv.y;
                    m0[4 * q + 2] = (s.z + bb.z) * cv0 * hv.z;
                    m0[4 * q + 3] = (s.w + bb.w) * cv0 * hv.w;
                }
            }
            if (ok1) {
                const float* hp = g_h + (size_t)ed1.y * DNF + c0;
#pragma unroll
                for (int q = 0; q < 4; ++q) {
                    float4 s = *(float4*)(stage + e1 * 132 + c0 + 4 * q);
                    float4 bb = *(float4*)(sB2 + c0 + 4 * q);
                    float4 hv = ldcg4(hp + 4 * q);
                    m1[4 * q + 0] = (s.x + bb.x) * cv1 * hv.x;
                    m1[4 * q + 1] = (s.y + bb.y) * cv1 * hv.y;
                    m1[4 * q + 2] = (s.z + bb.z) * cv1 * hv.z;
                    m1[4 * q + 3] = (s.w + bb.w) * cv1 * hv.w;
                }
            }
            if (ok0 && ok1 && ed0.z == ed1.z) {
                float* dp = g_agg + (size_t)ed0.z * DNF + c0;
#pragma unroll
                for (int q = 0; q < 4; ++q)
                    red_add_v4(dp + 4 * q, m0[4 * q] + m1[4 * q], m0[4 * q + 1] + m1[4 * q + 1],
                               m0[4 * q + 2] + m1[4 * q + 2], m0[4 * q + 3] + m1[4 * q + 3]);
            } else {
                if (ok0) {
                    float* dp = g_agg + (size_t)ed0.z * DNF + c0;
#pragma unroll
                    for (int q = 0; q < 4; ++q)
                        red_add_v4(dp + 4 * q, m0[4 * q], m0[4 * q + 1], m0[4 * q + 2], m0[4 * q + 3]);
                }
                if (ok1) {
                    float* dp = g_agg + (size_t)ed1.z * DNF + c0;
#pragma unroll
                    for (int q = 0; q < 4; ++q)
                        red_add_v4(dp + 4 * q, m1[4 * q], m1[4 * q + 1], m1[4 * q + 2], m1[4 * q + 3]);
                }
            }
        }
        // no trailing barrier: next GEMM1 reads sA (ready); ssp of next iter is
        // gated by the barrier after GEMM1, which orders it after this epilogue.
    }
}

// -------- Kernel 3: out = ssp(agg@lin2_w + lin2_b) @ lin_w + lin_b --------
extern "C" __global__ void __launch_bounds__(512, 1)
k_out(const float* __restrict__ w2, const float* __restrict__ b2,
      const float* __restrict__ w3, const float* __restrict__ b3,
      float* __restrict__ out) {
    extern __shared__ float smf[];
    float* sW2 = smf;
    float* sW3 = sW2 + DNF * DHID;
    float* sA  = sW3 + DHID * DHID;
    float* sB2 = sA + DNF * 130;
    float* sB3 = sB2 + 128;

    const int tid = threadIdx.x;
    const int rg = tid & 31, cg = tid >> 5;
    const int c0 = cg * 8;

    for (int i = tid; i < DNF * DHID / 4; i += 512)
        ((float4*)sW2)[i] = ((const float4*)w2)[i];
    for (int i = tid; i < DHID * DHID / 4; i += 512)
        ((float4*)sW3)[i] = ((const float4*)w3)[i];
    if (tid < DHID) { sB2[tid] = b2[tid]; sB3[tid] = b3[tid]; }

    const int ntiles = (NNODES + 127) / 128;
    for (int tile = blockIdx.x; tile < ntiles; tile += gridDim.x) {
        const int r0 = tile * 128;
        __syncthreads();
        {
            int e = tid >> 2, k0 = (tid & 3) << 5;
            int r = r0 + e;
            const float* src = g_agg + (size_t)r * DNF + k0;
#pragma unroll
            for (int i = 0; i < 8; ++i) {
                float4 v = (r < NNODES) ? ldcs4(src + 4 * i) : make_float4(0.f, 0.f, 0.f, 0.f);
                int k = k0 + 4 * i;
                sA[(k + 0) * 130 + e] = v.x;
                sA[(k + 1) * 130 + e] = v.y;
                sA[(k + 2) * 130 + e] = v.z;
                sA[(k + 3) * 130 + e] = v.w;
            }
        }
        __syncthreads();

        ull acc[4][4];
#pragma unroll
        for (int j = 0; j < 4; ++j)
#pragma unroll
            for (int p = 0; p < 4; ++p) acc[j][p] = 0ull;
        mm4x8<DNF>(sA, sW2, rg, c0, acc);
        __syncthreads();

#pragma unroll
        for (int p = 0; p < 4; ++p) {
            float bx = sB2[c0 + 2 * p], by = sB2[c0 + 2 * p + 1];
#pragma unroll
            for (int j = 0; j < 4; ++j) {
                float2 v = unpack2(acc[j][p]);
                int row = rg + 32 * j;
                sA[(c0 + 2 * p) * 130 + row] = ssp_f(v.x + bx);
                sA[(c0 + 2 * p + 1) * 130 + row] = ssp_f(v.y + by);
            }
        }
        __syncthreads();

#pragma unroll
        for (int j = 0; j < 4; ++j)
#pragma unroll
            for (int p = 0; p < 4; ++p) acc[j][p] = 0ull;
        mm4x8<DHID>(sA, sW3, rg, c0, acc);

#pragma unroll
        for (int j = 0; j < 4; ++j) {
            int r = r0 + rg + 32 * j;
            if (r < NNODES) {
                float2 v0 = unpack2(acc[j][0]), v1 = unpack2(acc[j][1]);
                float2 v2 = unpack2(acc[j][2]), v3 = unpack2(acc[j][3]);
                *(float4*)(out + (size_t)r * DHID + c0) =
                    make_float4(v0.x + sB3[c0 + 0], v0.y + sB3[c0 + 1],
                                v1.x + sB3[c0 + 2], v1.y + sB3[c0 + 3]);
                *(float4*)(out + (size_t)r * DHID + c0 + 4) =
                    make_float4(v2.x + sB3[c0 + 4], v2.y + sB3[c0 + 5],
                                v3.x + sB3[c0 + 6], v3.y + sB3[c0 + 7]);
            }
        }
    }
}

extern "C" void kernel_launch(void* const* d_in, const int* in_sizes, int n_in,
                              void* d_out, int out_size) {
    const float* x      = (const float*)d_in[0];
    const int*   ei     = (const int*)d_in[1];
    const float* elen   = (const float*)d_in[2];
    const float* eattr  = (const float*)d_in[3];
    const float* lin1_w = (const float*)d_in[4];
    const float* nn_w1  = (const float*)d_in[5];
    const float* nn_b1  = (const float*)d_in[6];
    const float* nn_w2  = (const float*)d_in[7];
    const float* nn_b2  = (const float*)d_in[8];
    const float* lin2_w = (const float*)d_in[9];
    const float* lin2_b = (const float*)d_in[10];
    const float* lin_w  = (const float*)d_in[11];
    const float* lin_b  = (const float*)d_in[12];
    float* out = (float*)d_out;

    size_t sm1 = (size_t)(DHID * 130) * 4;
    size_t sm3 = (size_t)(DNF * DHID + DHID * DHID + DNF * 130 + 2 * 128) * 4;

    cudaFuncSetAttribute(k_proj_zero, cudaFuncAttributeMaxDynamicSharedMemorySize, (int)sm1);
    cudaFuncSetAttribute(k_edge, cudaFuncAttributeMaxDynamicSharedMemorySize, SMEM_EDGE);
    cudaFuncSetAttribute(k_out, cudaFuncAttributeMaxDynamicSharedMemorySize, (int)sm3);

    k_proj_zero<<<304, 256, sm1>>>(x, lin1_w);   // 1: h + zero agg + zero hist
    k_count<<<304, 256>>>(ei, elen);             // 2
    k_scan<<<1, 1024>>>();                       // 3
    k_scatter<<<304, 256>>>(ei, elen);           // 4
    k_nop<<<1, 32>>>();                          // 5 (aligns ncu -s5 capture onto k_edge)
    k_edge<<<152, 512, SMEM_EDGE>>>(eattr, nn_w1, nn_b1, nn_w2, nn_b2);  // 6 <- profiled
    k_out<<<152, 512, sm3>>>(lin2_w, lin2_b, lin_w, lin_b, out);
}

// round 15
// speedup vs baseline: 1.9211x; 1.1605x over previous
#include <cuda_runtime.h>
#include <cuda_bf16.h>
#include <cstdint>

#define NNODES 50000
#define EEDGES 1600000
#define DHID 128
#define DNF 128
#define DNG 64
#define LN2 0.69314718055994530942f
#define FPI 3.14159265358979323846f

typedef unsigned long long ull;
typedef unsigned int uint;

// Scratch (static device arrays: allocation-free per harness rules)
__device__ float g_h[(size_t)NNODES * DNF];    // x @ lin1_w
__device__ float g_agg[(size_t)NNODES * DNF];  // segment_sum accumulator
__device__ int   g_cnt;                        // compacted edge count
__device__ int   g_hist[NNODES];               // per-dst edge count
__device__ int   g_off[NNODES];                // exclusive prefix (mutated by scatter)
__device__ int4  g_edge[EEDGES + 128];         // dst-sorted {eid, src, dst, C-bits} (padded)

// ---------------- helpers ----------------
__device__ __forceinline__ float ssp_f(float v) {
    return fmaxf(v, 0.0f) + __logf(1.0f + __expf(-fabsf(v))) - LN2;
}
__device__ __forceinline__ void red_add_v4(float* p, float a, float b, float c, float d) {
    asm volatile("red.global.add.v4.f32 [%0], {%1, %2, %3, %4};"
                 :: "l"(p), "f"(a), "f"(b), "f"(c), "f"(d) : "memory");
}
__device__ __forceinline__ ull pack2(float a) {
    ull r;
    asm("mov.b64 %0, {%1, %1};" : "=l"(r) : "f"(a));
    return r;
}
__device__ __forceinline__ float2 unpack2(ull v) {
    float2 f;
    asm("mov.b64 {%0, %1}, %2;" : "=f"(f.x), "=f"(f.y) : "l"(v));
    return f;
}
__device__ __forceinline__ void fma2(ull& d, ull a, ull b) {
    asm("fma.rn.f32x2 %0, %1, %2, %0;" : "+l"(d) : "l"(a), "l"(b));
}
__device__ __forceinline__ float4 ldcs4(const float* p) {
    float4 v;
    asm volatile("ld.global.cs.v4.f32 {%0,%1,%2,%3}, [%4];"
                 : "=f"(v.x), "=f"(v.y), "=f"(v.z), "=f"(v.w) : "l"(p));
    return v;
}
__device__ __forceinline__ float4 ldcg4(const float* p) {
    float4 v;
    asm volatile("ld.global.cg.v4.f32 {%0,%1,%2,%3}, [%4];"
                 : "=f"(v.x), "=f"(v.y), "=f"(v.z), "=f"(v.w) : "l"(p));
    return v;
}

// bf16 mma.sync: D(16x8,f32) += A(16x16)B(16x8)
__device__ __forceinline__ void mma_bf16(float d[4], uint a0, uint a1, uint a2, uint a3,
                                         uint b0, uint b1) {
    asm volatile(
        "mma.sync.aligned.m16n8k16.row.col.f32.bf16.bf16.f32 "
        "{%0,%1,%2,%3}, {%4,%5,%6,%7}, {%8,%9}, {%0,%1,%2,%3};"
        : "+f"(d[0]), "+f"(d[1]), "+f"(d[2]), "+f"(d[3])
        : "r"(a0), "r"(a1), "r"(a2), "r"(a3), "r"(b0), "r"(b1));
}
__device__ __forceinline__ void ldsm4(uint& r0, uint& r1, uint& r2, uint& r3, uint addr) {
    asm volatile("ldmatrix.sync.aligned.m8n8.x4.shared.b16 {%0,%1,%2,%3}, [%4];"
                 : "=r"(r0), "=r"(r1), "=r"(r2), "=r"(r3) : "r"(addr));
}

// split (x,y) -> packed bf16 hi pair + lo pair
__device__ __forceinline__ void splitpair(float x, float y, uint& h, uint& l) {
    __nv_bfloat162 hh = __floats2bfloat162_rn(x, y);
    float2 hf = __bfloat1622float2(hh);
    __nv_bfloat162 ll = __floats2bfloat162_rn(x - hf.x, y - hf.y);
    h = *reinterpret_cast<uint*>(&hh);
    l = *reinterpret_cast<uint*>(&ll);
}

// ---- scalar microkernels for k_proj / k_out ----
template <int K>
__device__ __forceinline__ void mm8x8g(const float* __restrict__ As,
                                       const float* __restrict__ Bg,
                                       int rg2, int c0, ull acc[4][8]) {
#pragma unroll 4
    for (int k = 0; k < K; ++k) {
        const float* ar = As + k * 130 + rg2;
        ull a0 = *(const ull*)(ar);
        ull a1 = *(const ull*)(ar + 32);
        ull a2 = *(const ull*)(ar + 64);
        ull a3 = *(const ull*)(ar + 96);
        const float4* bp = (const float4*)(Bg + k * 128 + c0);
        float4 b0 = __ldg(bp);
        float4 b1 = __ldg(bp + 1);
        ull bb[8] = {pack2(b0.x), pack2(b0.y), pack2(b0.z), pack2(b0.w),
                     pack2(b1.x), pack2(b1.y), pack2(b1.z), pack2(b1.w)};
#pragma unroll
        for (int c = 0; c < 8; ++c) {
            fma2(acc[0][c], a0, bb[c]);
            fma2(acc[1][c], a1, bb[c]);
            fma2(acc[2][c], a2, bb[c]);
            fma2(acc[3][c], a3, bb[c]);
        }
    }
}
template <int K>
__device__ __forceinline__ void mm4x8(const float* __restrict__ As,
                                      const float* __restrict__ Bs,
                                      int rg, int c0, ull acc[4][4]) {
#pragma unroll 4
    for (int k = 0; k < K; ++k) {
        const float* ar = As + k * 130 + rg;
        ull a0 = pack2(ar[0]);
        ull a1 = pack2(ar[32]);
        ull a2 = pack2(ar[64]);
        ull a3 = pack2(ar[96]);
        const float* br = Bs + k * 128 + c0;
        ulonglong2 b01 = *(const ulonglong2*)br;
        ulonglong2 b23 = *(const ulonglong2*)(br + 4);
        ull bb[4] = {b01.x, b01.y, b23.x, b23.y};
#pragma unroll
        for (int p = 0; p < 4; ++p) {
            fma2(acc[0][p], a0, bb[p]);
            fma2(acc[1][p], a1, bb[p]);
            fma2(acc[2][p], a2, bb[p]);
            fma2(acc[3][p], a3, bb[p]);
        }
    }
}

// ---------------- sort chain ----------------
extern "C" __global__ void __launch_bounds__(256)
k_count(const int* __restrict__ ei, const float* __restrict__ elen) {
    const int stride = gridDim.x * blockDim.x;
    for (int i = blockIdx.x * blockDim.x + threadIdx.x; i < EEDGES; i += stride) {
        float L = elen[i];
        if (L <= 10.0f && L >= 0.0f)
            atomicAdd(&g_hist[ei[EEDGES + i]], 1);
    }
}

extern "C" __global__ void __launch_bounds__(1024)
k_scan() {
    __shared__ int wsum[32];
    const int tid = threadIdx.x;
    const int lane = tid & 31, wid = tid >> 5;
    int running = 0;
    for (int base = 0; base < NNODES; base += 1024) {
        int idx = base + tid;
        int v = (idx < NNODES) ? g_hist[idx] : 0;
        int x = v;
#pragma unroll
        for (int o = 1; o < 32; o <<= 1) {
            int t = __shfl_up_sync(0xffffffffu, x, o);
            if (lane >= o) x += t;
        }
        if (lane == 31) wsum[wid] = x;
        __syncthreads();
        if (wid == 0) {
            int w = wsum[lane];
#pragma unroll
            for (int o = 1; o < 32; o <<= 1) {
                int t = __shfl_up_sync(0xffffffffu, w, o);
                if (lane >= o) w += t;
            }
            wsum[lane] = w;
        }
        __syncthreads();
        int woff = wid ? wsum[wid - 1] : 0;
        if (idx < NNODES) g_off[idx] = running + woff + x - v;
        running += wsum[31];
        __syncthreads();
    }
    if (tid == 0) g_cnt = running;
}

extern "C" __global__ void __launch_bounds__(256)
k_scatter(const int* __restrict__ ei, const float* __restrict__ elen) {
    const int stride = gridDim.x * blockDim.x;
    for (int i = blockIdx.x * blockDim.x + threadIdx.x; i < EEDGES; i += stride) {
        float L = elen[i];
        if (L <= 10.0f && L >= 0.0f) {
            int d = ei[EEDGES + i];
            int pos = atomicAdd(&g_off[d], 1);
            float C = 0.5f * (__cosf(L * (FPI / 10.0f)) + 1.0f);
            g_edge[pos] = make_int4(i, ei[i], d, __float_as_int(C));
        }
    }
}

// dummy so ncu's -s5 window (6th launch) lands on k_edge
extern "C" __global__ void k_nop() {}

// ---------------- Kernel 1: h = x @ lin1_w, zero g_agg + g_hist ----------------
extern "C" __global__ void __launch_bounds__(256, 2)
k_proj_zero(const float* __restrict__ x, const float* __restrict__ w1) {
    extern __shared__ float smf[];
    float* sX = smf;
    const int tid = threadIdx.x;
    const int cg = tid >> 4, rg = tid & 15;
    const int c0 = cg * 8, rg2 = rg * 2;

    const int ntiles = (NNODES + 127) / 128;
    for (int tile = blockIdx.x; tile < ntiles; tile += gridDim.x) {
        const int r0 = tile * 128;
        __syncthreads();
        {
            int e = tid >> 1, k0 = (tid & 1) << 6;
            int r = r0 + e;
            if (r < NNODES) {
                const float* src = x + (size_t)r * DHID + k0;
#pragma unroll
                for (int i = 0; i < 16; ++i) {
                    float4 v = ldcs4(src + 4 * i);
                    int k = k0 + 4 * i;
                    sX[(k + 0) * 130 + e] = v.x;
                    sX[(k + 1) * 130 + e] = v.y;
                    sX[(k + 2) * 130 + e] = v.z;
                    sX[(k + 3) * 130 + e] = v.w;
                }
            }
        }
        __syncthreads();
        ull acc[4][8];
#pragma unroll
        for (int j = 0; j < 4; ++j)
#pragma unroll
            for (int c = 0; c < 8; ++c) acc[j][c] = 0ull;
        mm8x8g<DHID>(sX, w1, rg2, c0, acc);
#pragma unroll
        for (int j = 0; j < 4; ++j) {
            int r = r0 + rg2 + 32 * j;
            float2 v0 = unpack2(acc[j][0]), v1 = unpack2(acc[j][1]);
            float2 v2 = unpack2(acc[j][2]), v3 = unpack2(acc[j][3]);
            float2 v4 = unpack2(acc[j][4]), v5 = unpack2(acc[j][5]);
            float2 v6 = unpack2(acc[j][6]), v7 = unpack2(acc[j][7]);
            if (r < NNODES) {
                *(float4*)(g_h + (size_t)r * DNF + c0) = make_float4(v0.x, v1.x, v2.x, v3.x);
                *(float4*)(g_h + (size_t)r * DNF + c0 + 4) = make_float4(v4.x, v5.x, v6.x, v7.x);
                *(float4*)(g_agg + (size_t)r * DNF + c0) = make_float4(0.f, 0.f, 0.f, 0.f);
                *(float4*)(g_agg + (size_t)r * DNF + c0 + 4) = make_float4(0.f, 0.f, 0.f, 0.f);
                if (cg == 0) g_hist[r] = 0;
            }
            if (r + 1 < NNODES) {
                *(float4*)(g_h + (size_t)(r + 1) * DNF + c0) = make_float4(v0.y, v1.y, v2.y, v3.y);
                *(float4*)(g_h + (size_t)(r + 1) * DNF + c0 + 4) = make_float4(v4.y, v5.y, v6.y, v7.y);
                *(float4*)(g_agg + (size_t)(r + 1) * DNF + c0) = make_float4(0.f, 0.f, 0.f, 0.f);
                *(float4*)(g_agg + (size_t)(r + 1) * DNF + c0 + 4) = make_float4(0.f, 0.f, 0.f, 0.f);
                if (cg == 0) g_hist[r + 1] = 0;
            }
        }
    }
}

// ---------------- Kernel 2: HMMA edge MLP (1024 thr, 32 warps, B via ldmatrix) -----------
#define ST64 72
#define ST128 136
#define OFF_B1  0
#define OFF_B2  512
#define OFF_W1H 1024
#define OFF_W1L (OFF_W1H + 128 * ST64 * 2)
#define OFF_W2H (OFF_W1L + 128 * ST64 * 2)
#define OFF_W2L (OFF_W2H + 128 * ST128 * 2)
#define OFF_SAH (OFF_W2L + 128 * ST128 * 2)
#define OFF_SAL (OFF_SAH + 128 * ST64 * 2)
#define OFF_STH (OFF_SAL + 128 * ST64 * 2)
#define OFF_STL (OFF_STH + 128 * ST128 * 2)
#define OFF_STAGE OFF_STH                       // f32 128x132 union over sT region
#define SMEM_EDGE (OFF_STL + 128 * ST128 * 2)   // 214016 B

extern "C" __global__ void __launch_bounds__(1024, 1)
k_edge(const float* __restrict__ edge_attr,
       const float* __restrict__ w1, const float* __restrict__ b1,
       const float* __restrict__ w2, const float* __restrict__ b2) {
    extern __shared__ __align__(16) char sm[];
    float* sB1 = (float*)(sm + OFF_B1);
    float* sB2 = (float*)(sm + OFF_B2);
    float* stage = (float*)(sm + OFF_STAGE);    // [128][132] f32

    const int tid = threadIdx.x;
    const int lane = tid & 31, wid = tid >> 5;
    const int g = lane >> 2, t = lane & 3;
    const int mw = (wid & 7) * 16;              // row strip (8 strips)
    const int nw = (wid >> 3) * 32;             // col quarter (4 quarters)

    // ldmatrix lane addressing: A/T fragments (row-major 16x16)
    const int arow = mw + (lane & 7) + ((lane >> 3) & 1) * 8;
    const int acol = ((lane >> 4) & 1) * 8;
    const uint sbase = (uint)__cvta_generic_to_shared(sm);
    const uint aSAH = sbase + OFF_SAH + (uint)((arow * ST64 + acol) * 2);
    const uint aSAL = sbase + OFF_SAL + (uint)((arow * ST64 + acol) * 2);
    const uint aSTH = sbase + OFF_STH + (uint)((arow * ST128 + acol) * 2);
    const uint aSTL = sbase + OFF_STL + (uint)((arow * ST128 + acol) * 2);

    // ldmatrix lane addressing: B fragments ([n][k] storage; x4 = 2 n-tiles x (klo,khi))
    const int bn = (lane & 7) + ((lane >> 4) & 1) * 8;   // n within 16-row pair group
    const int bk = ((lane >> 3) & 1) * 8;                // k lo/hi
    const uint aW1H0 = sbase + OFF_W1H + (uint)(((nw + bn) * ST64 + bk) * 2);
    const uint aW1H1 = sbase + OFF_W1H + (uint)(((nw + 16 + bn) * ST64 + bk) * 2);
    const uint aW1L0 = sbase + OFF_W1L + (uint)(((nw + bn) * ST64 + bk) * 2);
    const uint aW1L1 = sbase + OFF_W1L + (uint)(((nw + 16 + bn) * ST64 + bk) * 2);
    const uint aW2H0 = sbase + OFF_W2H + (uint)(((nw + bn) * ST128 + bk) * 2);
    const uint aW2H1 = sbase + OFF_W2H + (uint)(((nw + 16 + bn) * ST128 + bk) * 2);
    const uint aW2L0 = sbase + OFF_W2L + (uint)(((nw + bn) * ST128 + bk) * 2);
    const uint aW2L1 = sbase + OFF_W2L + (uint)(((nw + 16 + bn) * ST128 + bk) * 2);

    // ---- prologue: weights (transposed, hi/lo split) + biases ----
    for (int idx = tid; idx < DNG * DNF; idx += 1024) {    // w1[k][f] -> sW1[f][k]
        int k = idx >> 7, f = idx & 127;
        float v = w1[idx];
        __nv_bfloat16 h = __float2bfloat16(v);
        __nv_bfloat16 l = __float2bfloat16(v - __bfloat162float(h));
        ((__nv_bfloat16*)(sm + OFF_W1H))[f * ST64 + k] = h;
        ((__nv_bfloat16*)(sm + OFF_W1L))[f * ST64 + k] = l;
    }
    for (int idx = tid; idx < DNF * DNF; idx += 1024) {    // w2[f1][f2] -> sW2[f2][f1]
        int f1 = idx >> 7, f2 = idx & 127;
        float v = w2[idx];
        __nv_bfloat16 h = __float2bfloat16(v);
        __nv_bfloat16 l = __float2bfloat16(v - __bfloat162float(h));
        ((__nv_bfloat16*)(sm + OFF_W2H))[f2 * ST128 + f1] = h;
        ((__nv_bfloat16*)(sm + OFF_W2L))[f2 * ST128 + f1] = l;
    }
    if (tid < DNF) { sB1[tid] = b1[tid]; sB2[tid] = b2[tid]; }

    const int cnt = g_cnt;
    const int ntiles = (cnt + 127) >> 7;
    const int stride = gridDim.x;

    const int le = tid >> 3, lk0 = (tid & 7) << 3;   // A-load: 8 floats/thread

    auto ldg_tile = [&](int tile, float4 pf[2]) {
        int gi = (tile << 7) + le;
        int eid = (gi < cnt) ? __ldg(&g_edge[gi]).x : 0;
        const float* src = edge_attr + (size_t)eid * DNG + lk0;
        pf[0] = ldcs4(src);
        pf[1] = ldcs4(src + 4);
    };
    auto sts_tile = [&](const float4 pf[2]) {
        uint* dh = (uint*)(sm + OFF_SAH) + (le * ST64 + lk0) / 2;
        uint* dl = (uint*)(sm + OFF_SAL) + (le * ST64 + lk0) / 2;
#pragma unroll
        for (int i = 0; i < 2; ++i) {
            uint h0, l0, h1, l1;
            splitpair(pf[i].x, pf[i].y, h0, l0);
            splitpair(pf[i].z, pf[i].w, h1, l1);
            dh[2 * i] = h0; dh[2 * i + 1] = h1;
            dl[2 * i] = l0; dl[2 * i + 1] = l1;
        }
    };

    int tile = blockIdx.x;
    if (tile < ntiles) {
        float4 pf[2];
        ldg_tile(tile, pf);
        sts_tile(pf);
    }
    __syncthreads();

    for (; tile < ntiles; tile += stride) {
        const int eg0 = tile << 7;

        // ---- GEMM1 (K=64): d1[4 nt][4] ----
        float d1[4][4];
#pragma unroll
        for (int nt = 0; nt < 4; ++nt)
#pragma unroll
            for (int q = 0; q < 4; ++q) d1[nt][q] = 0.0f;
#pragma unroll
        for (int kc = 0; kc < 4; ++kc) {
            uint ah0, ah1, ah2, ah3, al0, al1, al2, al3;
            ldsm4(ah0, ah1, ah2, ah3, aSAH + kc * 32);
            ldsm4(al0, al1, al2, al3, aSAL + kc * 32);
#pragma unroll
            for (int p = 0; p < 2; ++p) {
                uint bh0, bh1, bh2, bh3, bl0v, bl1v, bl2v, bl3v;
                ldsm4(bh0, bh1, bh2, bh3, (p ? aW1H1 : aW1H0) + kc * 32);
                ldsm4(bl0v, bl1v, bl2v, bl3v, (p ? aW1L1 : aW1L0) + kc * 32);
                mma_bf16(d1[2 * p], ah0, ah1, ah2, ah3, bh0, bh1);
                mma_bf16(d1[2 * p], al0, al1, al2, al3, bh0, bh1);
                mma_bf16(d1[2 * p], ah0, ah1, ah2, ah3, bl0v, bl1v);
                mma_bf16(d1[2 * p + 1], ah0, ah1, ah2, ah3, bh2, bh3);
                mma_bf16(d1[2 * p + 1], al0, al1, al2, al3, bh2, bh3);
                mma_bf16(d1[2 * p + 1], ah0, ah1, ah2, ah3, bl2v, bl3v);
            }
        }
        __syncthreads();   // sA reads done

        // ---- prefetch next tile's A (8 regs) ----
        const int tnext = tile + stride;
        const bool have = tnext < ntiles;
        float4 pf[2];
        if (have) ldg_tile(tnext, pf);

        // ---- ssp(D1 + b1) -> sT hi/lo ----
#pragma unroll
        for (int nt = 0; nt < 4; ++nt) {
            int c = nw + nt * 8 + 2 * t;
            float b0v = sB1[c], b1v = sB1[c + 1];
            uint h, l;
            splitpair(ssp_f(d1[nt][0] + b0v), ssp_f(d1[nt][1] + b1v), h, l);
            *(uint*)(sm + OFF_STH + ((mw + g) * ST128 + c) * 2) = h;
            *(uint*)(sm + OFF_STL + ((mw + g) * ST128 + c) * 2) = l;
            splitpair(ssp_f(d1[nt][2] + b0v), ssp_f(d1[nt][3] + b1v), h, l);
            *(uint*)(sm + OFF_STH + ((mw + g + 8) * ST128 + c) * 2) = h;
            *(uint*)(sm + OFF_STL + ((mw + g + 8) * ST128 + c) * 2) = l;
        }
        __syncthreads();   // sT ready

        // ---- GEMM2 (K=128): d2[4 nt][4] ----
        float d2[4][4];
#pragma unroll
        for (int nt = 0; nt < 4; ++nt)
#pragma unroll
            for (int q = 0; q < 4; ++q) d2[nt][q] = 0.0f;
#pragma unroll
        for (int kc = 0; kc < 8; ++kc) {
            uint ah0, ah1, ah2, ah3, al0, al1, al2, al3;
            ldsm4(ah0, ah1, ah2, ah3, aSTH + kc * 32);
            ldsm4(al0, al1, al2, al3, aSTL + kc * 32);
#pragma unroll
            for (int p = 0; p < 2; ++p) {
                uint bh0, bh1, bh2, bh3, bl0v, bl1v, bl2v, bl3v;
                ldsm4(bh0, bh1, bh2, bh3, (p ? aW2H1 : aW2H0) + kc * 32);
                ldsm4(bl0v, bl1v, bl2v, bl3v, (p ? aW2L1 : aW2L0) + kc * 32);
                mma_bf16(d2[2 * p], ah0, ah1, ah2, ah3, bh0, bh1);
                mma_bf16(d2[2 * p], al0, al1, al2, al3, bh0, bh1);
                mma_bf16(d2[2 * p], ah0, ah1, ah2, ah3, bl0v, bl1v);
                mma_bf16(d2[2 * p + 1], ah0, ah1, ah2, ah3, bh2, bh3);
                mma_bf16(d2[2 * p + 1], al0, al1, al2, al3, bh2, bh3);
                mma_bf16(d2[2 * p + 1], ah0, ah1, ah2, ah3, bl2v, bl3v);
            }
        }
        __syncthreads();   // sT reads done -> stage/sA writable

        // ---- stage D2 + store prefetched A ----
#pragma unroll
        for (int nt = 0; nt < 4; ++nt) {
            int c = nw + nt * 8 + 2 * t;
            *(float2*)(stage + (mw + g) * 132 + c) = make_float2(d2[nt][0], d2[nt][1]);
            *(float2*)(stage + (mw + g + 8) * 132 + c) = make_float2(d2[nt][2], d2[nt][3]);
        }
        if (have) sts_tile(pf);
        __syncthreads();   // stage + sA ready

        // ---- epilogue: pair/thread, dst-merged REDs ----
        {
            int pe = tid >> 4;                 // edge pair 0..63
            int c0 = (tid & 15) * 8;           // 8 cols
            int e0 = 2 * pe, e1 = 2 * pe + 1;
            int gi0 = eg0 + e0, gi1 = eg0 + e1;
            int4 ed0 = __ldg(&g_edge[gi0]);
            int4 ed1 = __ldg(&g_edge[gi1]);
            float cv0 = __int_as_float(ed0.w);
            float cv1 = __int_as_float(ed1.w);
            bool ok0 = (gi0 < cnt) && (cv0 != 0.0f);
            bool ok1 = (gi1 < cnt) && (cv1 != 0.0f);
            float m0[8], m1[8];
            if (ok0) {
                const float* hp = g_h + (size_t)ed0.y * DNF + c0;
#pragma unroll
                for (int q = 0; q < 2; ++q) {
                    float4 s = *(float4*)(stage + e0 * 132 + c0 + 4 * q);
                    float4 bb = *(float4*)(sB2 + c0 + 4 * q);
                    float4 hv = ldcg4(hp + 4 * q);
                    m0[4 * q + 0] = (s.x + bb.x) * cv0 * hv.x;
                    m0[4 * q + 1] = (s.y + bb.y) * cv0 * hv.y;
                    m0[4 * q + 2] = (s.z + bb.z) * cv0 * hv.z;
                    m0[4 * q + 3] = (s.w + bb.w) * cv0 * hv.w;
                }
            }
            if (ok1) {
                const float* hp = g_h + (size_t)ed1.y * DNF + c0;
#pragma unroll
                for (int q = 0; q < 2; ++q) {
                    float4 s = *(float4*)(stage + e1 * 132 + c0 + 4 * q);
                    float4 bb = *(float4*)(sB2 + c0 + 4 * q);
                    float4 hv = ldcg4(hp + 4 * q);
                    m1[4 * q + 0] = (s.x + bb.x) * cv1 * hv.x;
                    m1[4 * q + 1] = (s.y + bb.y) * cv1 * hv.y;
                    m1[4 * q + 2] = (s.z + bb.z) * cv1 * hv.z;
                    m1[4 * q + 3] = (s.w + bb.w) * cv1 * hv.w;
                }
            }
            if (ok0 && ok1 && ed0.z == ed1.z) {
                float* dp = g_agg + (size_t)ed0.z * DNF + c0;
                red_add_v4(dp, m0[0] + m1[0], m0[1] + m1[1], m0[2] + m1[2], m0[3] + m1[3]);
                red_add_v4(dp + 4, m0[4] + m1[4], m0[5] + m1[5], m0[6] + m1[6], m0[7] + m1[7]);
            } else {
                if (ok0) {
                    float* dp = g_agg + (size_t)ed0.z * DNF + c0;
                    red_add_v4(dp, m0[0], m0[1], m0[2], m0[3]);
                    red_add_v4(dp + 4, m0[4], m0[5], m0[6], m0[7]);
                }
                if (ok1) {
                    float* dp = g_agg + (size_t)ed1.z * DNF + c0;
                    red_add_v4(dp, m1[0], m1[1], m1[2], m1[3]);
                    red_add_v4(dp + 4, m1[4], m1[5], m1[6], m1[7]);
                }
            }
        }
        // next GEMM1 reads sA (ready); next ssp is ordered after this epilogue
        // by the barrier following GEMM1.
    }
}

// -------- Kernel 3: out = ssp(agg@lin2_w + lin2_b) @ lin_w + lin_b --------
extern "C" __global__ void __launch_bounds__(512, 1)
k_out(const float* __restrict__ w2, const float* __restrict__ b2,
      const float* __restrict__ w3, const float* __restrict__ b3,
      float* __restrict__ out) {
    extern __shared__ float smf[];
    float* sW2 = smf;
    float* sW3 = sW2 + DNF * DHID;
    float* sA  = sW3 + DHID * DHID;
    float* sB2 = sA + DNF * 130;
    float* sB3 = sB2 + 128;

    const int tid = threadIdx.x;
    const int rg = tid & 31, cg = tid >> 5;
    const int c0 = cg * 8;

    for (int i = tid; i < DNF * DHID / 4; i += 512)
        ((float4*)sW2)[i] = ((const float4*)w2)[i];
    for (int i = tid; i < DHID * DHID / 4; i += 512)
        ((float4*)sW3)[i] = ((const float4*)w3)[i];
    if (tid < DHID) { sB2[tid] = b2[tid]; sB3[tid] = b3[tid]; }

    const int ntiles = (NNODES + 127) / 128;
    for (int tile = blockIdx.x; tile < ntiles; tile += gridDim.x) {
        const int r0 = tile * 128;
        __syncthreads();
        {
            int e = tid >> 2, k0 = (tid & 3) << 5;
            int r = r0 + e;
            const float* src = g_agg + (size_t)r * DNF + k0;
#pragma unroll
            for (int i = 0; i < 8; ++i) {
                float4 v = (r < NNODES) ? ldcs4(src + 4 * i) : make_float4(0.f, 0.f, 0.f, 0.f);
                int k = k0 + 4 * i;
                sA[(k + 0) * 130 + e] = v.x;
                sA[(k + 1) * 130 + e] = v.y;
                sA[(k + 2) * 130 + e] = v.z;
                sA[(k + 3) * 130 + e] = v.w;
            }
        }
        __syncthreads();

        ull acc[4][4];
#pragma unroll
        for (int j = 0; j < 4; ++j)
#pragma unroll
            for (int p = 0; p < 4; ++p) acc[j][p] = 0ull;
        mm4x8<DNF>(sA, sW2, rg, c0, acc);
        __syncthreads();

#pragma unroll
        for (int p = 0; p < 4; ++p) {
            float bx = sB2[c0 + 2 * p], by = sB2[c0 + 2 * p + 1];
#pragma unroll
            for (int j = 0; j < 4; ++j) {
                float2 v = unpack2(acc[j][p]);
                int row = rg + 32 * j;
                sA[(c0 + 2 * p) * 130 + row] = ssp_f(v.x + bx);
                sA[(c0 + 2 * p + 1) * 130 + row] = ssp_f(v.y + by);
            }
        }
        __syncthreads();

#pragma unroll
        for (int j = 0; j < 4; ++j)
#pragma unroll
            for (int p = 0; p < 4; ++p) acc[j][p] = 0ull;
        mm4x8<DHID>(sA, sW3, rg, c0, acc);

#pragma unroll
        for (int j = 0; j < 4; ++j) {
            int r = r0 + rg + 32 * j;
            if (r < NNODES) {
                float2 v0 = unpack2(acc[j][0]), v1 = unpack2(acc[j][1]);
                float2 v2 = unpack2(acc[j][2]), v3 = unpack2(acc[j][3]);
                *(float4*)(out + (size_t)r * DHID + c0) =
                    make_float4(v0.x + sB3[c0 + 0], v0.y + sB3[c0 + 1],
                                v1.x + sB3[c0 + 2], v1.y + sB3[c0 + 3]);
                *(float4*)(out + (size_t)r * DHID + c0 + 4) =
                    make_float4(v2.x + sB3[c0 + 4], v2.y + sB3[c0 + 5],
                                v3.x + sB3[c0 + 6], v3.y + sB3[c0 + 7]);
            }
        }
    }
}

extern "C" void kernel_launch(void* const* d_in, const int* in_sizes, int n_in,
                              void* d_out, int out_size) {
    const float* x      = (const float*)d_in[0];
    const int*   ei     = (const int*)d_in[1];
    const float* elen   = (const float*)d_in[2];
    const float* eattr  = (const float*)d_in[3];
    const float* lin1_w = (const float*)d_in[4];
    const float* nn_w1  = (const float*)d_in[5];
    const float* nn_b1  = (const float*)d_in[6];
    const float* nn_w2  = (const float*)d_in[7];
    const float* nn_b2  = (const float*)d_in[8];
    const float* lin2_w = (const float*)d_in[9];
    const float* lin2_b = (const float*)d_in[10];
    const float* lin_w  = (const float*)d_in[11];
    const float* lin_b  = (const float*)d_in[12];
    float* out = (float*)d_out;

    size_t sm1 = (size_t)(DHID * 130) * 4;
    size_t sm3 = (size_t)(DNF * DHID + DHID * DHID + DNF * 130 + 2 * 128) * 4;

    cudaFuncSetAttribute(k_proj_zero, cudaFuncAttributeMaxDynamicSharedMemorySize, (int)sm1);
    cudaFuncSetAttribute(k_edge, cudaFuncAttributeMaxDynamicSharedMemorySize, SMEM_EDGE);
    cudaFuncSetAttribute(k_out, cudaFuncAttributeMaxDynamicSharedMemorySize, (int)sm3);

    k_proj_zero<<<304, 256, sm1>>>(x, lin1_w);   // 1
    k_count<<<304, 256>>>(ei, elen);             // 2
    k_scan<<<1, 1024>>>();                       // 3
    k_scatter<<<304, 256>>>(ei, elen);           // 4
    k_nop<<<1, 32>>>();                          // 5 (aligns ncu -s5 capture onto k_edge)
    k_edge<<<152, 1024, SMEM_EDGE>>>(eattr, nn_w1, nn_b1, nn_w2, nn_b2);  // 6 <- profiled
    k_out<<<152, 512, sm3>>>(lin2_w, lin2_b, lin_w, lin_b, out);
}